// round 13
// baseline (speedup 1.0000x reference)
#include <cuda_runtime.h>
#include <math.h>

// KineticsRNN R13: R5 pipeline structure, 576 threads (18 warps/SM), 4-way K-split.
// mat 512 threads: (i=t>>2, c=t&3) owns gate rows (r_i,z_i,n_i) for K-quarter c;
// 2-round shfl butterfly -> thread ends owning batch b=c; h_old in a register.
// aux 64 threads: tail (head+theta+RK4+outputs) + lift (2 rows/thread), overlapped
// with mat's gh. W_hh layout: pitch 144, chunk stride 36 -> conflict-free LDS.128
// with lane = 4i+c (phase banks 16i+4c cover all 32 banks).

#define THREADS 576
#define MATT 512
#define WPIT 144      // W_hh row pitch (words), == 16 mod 32
#define WCH 36        // K-chunk stride (words), == 4 mod 32
#define HPIT 132      // sH / sWhd row pitch
#define LPIT 36       // sLift row pitch

#define SMEM_FLOATS (384*WPIT + 4*HPIT + 4*LPIT + 5*HPIT + 16 + 16 + 16)
#define SMEM_BYTES  (SMEM_FLOATS*4)

typedef unsigned long long u64;

__device__ __forceinline__ u64 fma2(u64 a, u64 b, u64 c) {
    u64 d;
    asm("fma.rn.f32x2 %0, %1, %2, %3;" : "=l"(d) : "l"(a), "l"(b), "l"(c));
    return d;
}
__device__ __forceinline__ float f2sum(u64 v) {
    float2 f;
    asm("mov.b64 {%0, %1}, %2;" : "=f"(f.x), "=f"(f.y) : "l"(v));
    return f.x + f.y;
}
__device__ __forceinline__ float sigm(float x) { return __fdividef(1.f, 1.f + __expf(-x)); }
__device__ __forceinline__ float tanh_f(float x) { return 1.f - __fdividef(2.f, __expf(2.f*x) + 1.f); }

__global__ __launch_bounds__(THREADS, 1)
void krnn_kernel(const float* __restrict__ y0,
                 const float* __restrict__ u_seq,
                 const float* __restrict__ dt_seq,
                 const float* __restrict__ y_seq,
                 const float* __restrict__ W_lift,
                 const float* __restrict__ b_lift,
                 const float* __restrict__ W_ih,
                 const float* __restrict__ W_hh,
                 const float* __restrict__ b_ih,
                 const float* __restrict__ b_hh,
                 const float* __restrict__ W_head,
                 const float* __restrict__ b_head,
                 const float* __restrict__ u2y,
                 float* __restrict__ out,
                 int B, int K)
{
    extern __shared__ float sm[];
    float* sWhh  = sm;                       // 384*144 (4 chunks/row @ +36)
    float* sH    = sWhh + 384*WPIT;          // 4*132 (chunk c at +32c)
    float* sLift = sH + 4*HPIT;              // 4*36 (chunk c at +8c)
    float* sWhd  = sLift + 4*LPIT;           // 5*132
    float* sU    = sWhd + 5*HPIT;            // 4*4
    float* sYobs = sU + 16;
    float* sYtf  = sYobs + 16;

    const int t   = threadIdx.x;
    const int bg0 = blockIdx.x * 4;

    // ---- stage W_hh: word(row,k) = row*144 + 36*(k>>5) + (k&31) ----
    {
        const float4* src = (const float4*)W_hh;
        for (int idx = t; idx < 384*32; idx += THREADS) {
            int row = idx >> 5, kb = idx & 31;
            int dst = row*WPIT + WCH*(kb >> 3) + 4*(kb & 7);
            *(float4*)(sWhh + dst) = src[idx];
        }
    }
    for (int idx = t; idx < 5*128; idx += THREADS)
        sWhd[(idx/128)*HPIT + (idx%128)] = W_head[idx];

    // ================= mat state (512 threads) =================
    const int i = t >> 2, c = t & 3;
    u64 wihr[4], wihz[4], wihn[4];
    float cr = 0, cz = 0, bxn = 0, bhn = 0;
    float h_old = 0.f;
    if (t < MATT) {
        const ulonglong2* pr = (const ulonglong2*)(W_ih + (size_t)i*32 + 8*c);
        const ulonglong2* pz = (const ulonglong2*)(W_ih + (size_t)(128+i)*32 + 8*c);
        const ulonglong2* pn = (const ulonglong2*)(W_ih + (size_t)(256+i)*32 + 8*c);
#pragma unroll
        for (int j = 0; j < 2; j++) {
            ulonglong2 vr = pr[j]; wihr[2*j] = vr.x; wihr[2*j+1] = vr.y;
            ulonglong2 vz = pz[j]; wihz[2*j] = vz.x; wihz[2*j+1] = vz.y;
            ulonglong2 vn = pn[j]; wihn[2*j] = vn.x; wihn[2*j+1] = vn.y;
        }
        cr  = b_ih[i] + b_hh[i];
        cz  = b_ih[128+i] + b_hh[128+i];
        bxn = b_ih[256+i];
        bhn = b_hh[256+i];
    }

    // ================= aux state (64 threads, warps 16-17) =================
    const int g   = t - MATT;
    const int hbh = g / 5, hph = g % 5;      // head map (g<20)
    const int lr  = g >> 2, lbb = g & 3;     // lift: rows lr, lr+16; batch lbb
    float bhd = 0.f;
    float wlA0=0,wlA1=0,wlA2=0,wlA3=0,wlA4=0,wlA5=0,blfA=0;
    float wlB0=0,wlB1=0,wlB2=0,wlB3=0,wlB4=0,wlB5=0,blfB=0;
    float yf0=0,yf1=0,yf2=0,yf3=0,yf4=0;
    float J00=0,J01=0,J02=0,J10=0,J11=0,J12=0,J20=0,J21=0,J22=0;
    float cu0=0,cu1=0,cu2=0,cdt=0;
    if (t >= MATT) {
        if (g < 20) bhd = b_head[hph];
        wlA0=W_lift[lr*6+0]; wlA1=W_lift[lr*6+1]; wlA2=W_lift[lr*6+2];
        wlA3=W_lift[lr*6+3]; wlA4=W_lift[lr*6+4]; wlA5=W_lift[lr*6+5];
        blfA=b_lift[lr];
        int lr2 = lr + 16;
        wlB0=W_lift[lr2*6+0]; wlB1=W_lift[lr2*6+1]; wlB2=W_lift[lr2*6+2];
        wlB3=W_lift[lr2*6+3]; wlB4=W_lift[lr2*6+4]; wlB5=W_lift[lr2*6+5];
        blfB=b_lift[lr2];
        if (g < 4) {
            int bg = bg0 + g;
            yf0 = y0[bg*3+0]; yf2 = y0[bg*3+1]; yf4 = y0[bg*3+2];
            J00=u2y[0];J01=u2y[1];J02=u2y[2];J10=u2y[3];J11=u2y[4];J12=u2y[5];
            J20=u2y[6];J21=u2y[7];J22=u2y[8];
            const float* up = u_seq + (size_t)bg*K*3;
            cu0=up[0]; cu1=up[1]; cu2=up[2];
            cdt = dt_seq[(size_t)bg*K];
            sU[g*4+0]=cu0; sU[g*4+1]=cu1; sU[g*4+2]=cu2;
            sYobs[g*4+0]=yf0; sYobs[g*4+1]=yf2; sYobs[g*4+2]=yf4;
        }
    }
    for (int idx = t; idx < 4*HPIT; idx += THREADS) sH[idx] = 0.f;
    __syncthreads();

    // ---- prologue: lift(0) (aux, 2 rows/thread) ----
    if (t >= MATT) {
        const float* ub = sU + lbb*4;
        const float* yb = sYobs + lbb*4;
        float sA = blfA;
        sA=fmaf(wlA0,ub[0],sA); sA=fmaf(wlA1,ub[1],sA); sA=fmaf(wlA2,ub[2],sA);
        sA=fmaf(wlA3,yb[0],sA); sA=fmaf(wlA4,yb[1],sA); sA=fmaf(wlA5,yb[2],sA);
        sLift[lbb*LPIT + lr] = sA * sigm(sA);
        float sB = blfB;
        sB=fmaf(wlB0,ub[0],sB); sB=fmaf(wlB1,ub[1],sB); sB=fmaf(wlB2,ub[2],sB);
        sB=fmaf(wlB3,yb[0],sB); sB=fmaf(wlB4,yb[1],sB); sB=fmaf(wlB5,yb[2],sB);
        sLift[lbb*LPIT + 16 + lr] = sB * sigm(sB);
    }
    __syncthreads();

    const size_t thb = (size_t)B*K*3;
    const int c0 = c & 1, c1 = c >> 1;

    // gh accumulators (zero => gh(0)=0)
    u64 aR0=0,aR1=0,aR2=0,aR3=0, aZ0=0,aZ1=0,aZ2=0,aZ3=0, aN0=0,aN1=0,aN2=0,aN3=0;
    float nu0=0,nu1=0,nu2=0,ndt=0,nt0=0,nt1=0,nt2=0;
    bool nflag = false;

    for (int k = 0; k < K; k++) {
        if (t < MATT) {
            // ---- P1: gx(k) (r,z merged into aR/aZ; n part in aX) ----
            u64 aX0=0,aX1=0,aX2=0,aX3=0;
            {
                const ulonglong2* l0 = (const ulonglong2*)(sLift + 0*LPIT + 8*c);
                const ulonglong2* l1 = (const ulonglong2*)(sLift + 1*LPIT + 8*c);
                const ulonglong2* l2 = (const ulonglong2*)(sLift + 2*LPIT + 8*c);
                const ulonglong2* l3 = (const ulonglong2*)(sLift + 3*LPIT + 8*c);
#pragma unroll
                for (int j = 0; j < 2; j++) {
                    u64 wa=wihr[2*j], wb=wihr[2*j+1];
                    u64 za=wihz[2*j], zb=wihz[2*j+1];
                    u64 na=wihn[2*j], nb=wihn[2*j+1];
                    ulonglong2 v0=l0[j];
                    aR0=fma2(wa,v0.x,aR0); aR0=fma2(wb,v0.y,aR0);
                    aZ0=fma2(za,v0.x,aZ0); aZ0=fma2(zb,v0.y,aZ0);
                    aX0=fma2(na,v0.x,aX0); aX0=fma2(nb,v0.y,aX0);
                    ulonglong2 v1=l1[j];
                    aR1=fma2(wa,v1.x,aR1); aR1=fma2(wb,v1.y,aR1);
                    aZ1=fma2(za,v1.x,aZ1); aZ1=fma2(zb,v1.y,aZ1);
                    aX1=fma2(na,v1.x,aX1); aX1=fma2(nb,v1.y,aX1);
                    ulonglong2 v2=l2[j];
                    aR2=fma2(wa,v2.x,aR2); aR2=fma2(wb,v2.y,aR2);
                    aZ2=fma2(za,v2.x,aZ2); aZ2=fma2(zb,v2.y,aZ2);
                    aX2=fma2(na,v2.x,aX2); aX2=fma2(nb,v2.y,aX2);
                    ulonglong2 v3=l3[j];
                    aR3=fma2(wa,v3.x,aR3); aR3=fma2(wb,v3.y,aR3);
                    aZ3=fma2(za,v3.x,aZ3); aZ3=fma2(zb,v3.y,aZ3);
                    aX3=fma2(na,v3.x,aX3); aX3=fma2(nb,v3.y,aX3);
                }
            }
            // ---- 2-round butterfly: totals for batch b=c ----
            float pR0=f2sum(aR0),pR1=f2sum(aR1),pR2=f2sum(aR2),pR3=f2sum(aR3);
            float pZ0=f2sum(aZ0),pZ1=f2sum(aZ1),pZ2=f2sum(aZ2),pZ3=f2sum(aZ3);
            float pN0=f2sum(aN0),pN1=f2sum(aN1),pN2=f2sum(aN2),pN3=f2sum(aN3);
            float pX0=f2sum(aX0),pX1=f2sum(aX1),pX2=f2sum(aX2),pX3=f2sum(aX3);
            // round 1 (xor 1): keep batches with (b&1)==c0
            float tR0 = (c0?pR1:pR0) + __shfl_xor_sync(0xffffffffu, c0?pR0:pR1, 1);
            float tR2 = (c0?pR3:pR2) + __shfl_xor_sync(0xffffffffu, c0?pR2:pR3, 1);
            float tZ0 = (c0?pZ1:pZ0) + __shfl_xor_sync(0xffffffffu, c0?pZ0:pZ1, 1);
            float tZ2 = (c0?pZ3:pZ2) + __shfl_xor_sync(0xffffffffu, c0?pZ2:pZ3, 1);
            float tN0 = (c0?pN1:pN0) + __shfl_xor_sync(0xffffffffu, c0?pN0:pN1, 1);
            float tN2 = (c0?pN3:pN2) + __shfl_xor_sync(0xffffffffu, c0?pN2:pN3, 1);
            float tX0 = (c0?pX1:pX0) + __shfl_xor_sync(0xffffffffu, c0?pX0:pX1, 1);
            float tX2 = (c0?pX3:pX2) + __shfl_xor_sync(0xffffffffu, c0?pX2:pX3, 1);
            // round 2 (xor 2): keep batch with (b>>1)==c1  -> final batch = c
            float TR = (c1?tR2:tR0) + __shfl_xor_sync(0xffffffffu, c1?tR0:tR2, 2);
            float TZ = (c1?tZ2:tZ0) + __shfl_xor_sync(0xffffffffu, c1?tZ0:tZ2, 2);
            float TN = (c1?tN2:tN0) + __shfl_xor_sync(0xffffffffu, c1?tN0:tN2, 2);
            float TX = (c1?tX2:tX0) + __shfl_xor_sync(0xffffffffu, c1?tX0:tX2, 2);
            // ---- P2: gates + h for batch c (h_old in register) ----
            {
                float r = sigm(TR + cr);
                float z = sigm(TZ + cz);
                float n = tanh_f(TX + bxn + r*(TN + bhn));
                h_old = n + z*(h_old - n);
                sH[c*HPIT + i] = h_old;
            }
            aR0=aR1=aR2=aR3=0; aZ0=aZ1=aZ2=aZ3=0; aN0=aN1=aN2=aN3=0;
        } else {
            // ---- prefetch step-(k+1) inputs ----
            nflag = false;
            if (g < 4 && (k+1) < K) {
                int bg = bg0 + g;
                const float* up = u_seq + ((size_t)bg*K + (k+1))*3;
                nu0=up[0]; nu1=up[1]; nu2=up[2];
                ndt = dt_seq[(size_t)bg*K + (k+1)];
                nflag = ((k+1) % 50) == 0;
                if (nflag) {
                    const float* yp = y_seq + ((size_t)bg*K + k)*3;
                    nt0=yp[0]; nt1=yp[1]; nt2=yp[2];
                }
            }
        }
        __syncthreads();   // BAR_A: sH = h(k) visible

        if (t < MATT) {
            // ---- gh(k+1) = W_hh @ h(k), K-quarter c, all 4 batches ----
            const ulonglong2* wR = (const ulonglong2*)(sWhh + i*WPIT + WCH*c);
            const ulonglong2* wZ = (const ulonglong2*)(sWhh + (128+i)*WPIT + WCH*c);
            const ulonglong2* wN = (const ulonglong2*)(sWhh + (256+i)*WPIT + WCH*c);
            const ulonglong2* x0 = (const ulonglong2*)(sH + 0*HPIT + 32*c);
            const ulonglong2* x1 = (const ulonglong2*)(sH + 1*HPIT + 32*c);
            const ulonglong2* x2 = (const ulonglong2*)(sH + 2*HPIT + 32*c);
            const ulonglong2* x3 = (const ulonglong2*)(sH + 3*HPIT + 32*c);
#pragma unroll
            for (int j = 0; j < 8; j++) {
                ulonglong2 wr=wR[j], wz=wZ[j], wn=wN[j];
                ulonglong2 v0=x0[j];
                aR0=fma2(wr.x,v0.x,aR0); aR0=fma2(wr.y,v0.y,aR0);
                aZ0=fma2(wz.x,v0.x,aZ0); aZ0=fma2(wz.y,v0.y,aZ0);
                aN0=fma2(wn.x,v0.x,aN0); aN0=fma2(wn.y,v0.y,aN0);
                ulonglong2 v1=x1[j];
                aR1=fma2(wr.x,v1.x,aR1); aR1=fma2(wr.y,v1.y,aR1);
                aZ1=fma2(wz.x,v1.x,aZ1); aZ1=fma2(wz.y,v1.y,aZ1);
                aN1=fma2(wn.x,v1.x,aN1); aN1=fma2(wn.y,v1.y,aN1);
                ulonglong2 v2=x2[j];
                aR2=fma2(wr.x,v2.x,aR2); aR2=fma2(wr.y,v2.y,aR2);
                aZ2=fma2(wz.x,v2.x,aZ2); aZ2=fma2(wz.y,v2.y,aZ2);
                aN2=fma2(wn.x,v2.x,aN2); aN2=fma2(wn.y,v2.y,aN2);
                ulonglong2 v3=x3[j];
                aR3=fma2(wr.x,v3.x,aR3); aR3=fma2(wr.y,v3.y,aR3);
                aZ3=fma2(wz.x,v3.x,aZ3); aZ3=fma2(wz.y,v3.y,aZ3);
                aN3=fma2(wn.x,v3.x,aN3); aN3=fma2(wn.y,v3.y,aN3);
            }
        } else {
            // ---- tail(k): head + theta + RK4 + outputs ----
            float thv = 0.f;
            if (g < 20) {
                u64 s0 = 0, s1 = 0;
#pragma unroll
                for (int ch = 0; ch < 4; ch++) {
                    const ulonglong2* hr = (const ulonglong2*)(sH + hbh*HPIT + 32*ch);
                    const ulonglong2* wp = (const ulonglong2*)(sWhd + hph*HPIT + 32*ch);
#pragma unroll
                    for (int jb = 0; jb < 8; jb++) {
                        ulonglong2 h4 = hr[jb];
                        ulonglong2 w4 = wp[jb];
                        s0 = fma2(w4.x, h4.x, s0);
                        s1 = fma2(w4.y, h4.y, s1);
                    }
                }
                float s = f2sum(s0) + f2sum(s1) + bhd;
                thv = 0.001f + 1.999f * sigm(s);
                out[thb + ((size_t)(bg0 + hbh)*K + k)*5 + hph] = thv;
            }
            if (g < 32) {   // warp 16 only
                float th0 = __shfl_sync(0xffffffffu, thv, g*5+0);
                float th1 = __shfl_sync(0xffffffffu, thv, g*5+1);
                float th2 = __shfl_sync(0xffffffffu, thv, g*5+2);
                float th3 = __shfl_sync(0xffffffffu, thv, g*5+3);
                float th4 = __shfl_sync(0xffffffffu, thv, g*5+4);
                if (g < 4) {
                    int bg = bg0 + g;
                    yf0 += cu0*J00 + cu1*J10 + cu2*J20;
                    yf2 += cu0*J01 + cu1*J11 + cu2*J21;
                    yf4 += cu0*J02 + cu1*J12 + cu2*J22;
                    float h = cdt, hh = 0.5f*h;
#define RHS(A_,Bv,C_,D_,E_,d0,d1,d2,d3,d4) { \
    float r1=th0*(A_)*(Bv); float r2=th1*(C_); float r3=th2*(C_)*(D_); \
    float r4=th3*(E_); float r5=th4*(A_); \
    d0=-r1-r5; d1=-r1+r2; d2=r1-r2-r3; d3=-r3+r4; d4=r3-r4+r5; }
                    float a0,a1,a2,a3,a4;
                    RHS(yf0,yf1,yf2,yf3,yf4,a0,a1,a2,a3,a4);
                    float t0=yf0+hh*a0,t1=yf1+hh*a1,t2=yf2+hh*a2,t3=yf3+hh*a3,t4=yf4+hh*a4;
                    float b0,b1,b2,b3,b4v;
                    RHS(t0,t1,t2,t3,t4,b0,b1,b2,b3,b4v);
                    t0=yf0+hh*b0;t1=yf1+hh*b1;t2=yf2+hh*b2;t3=yf3+hh*b3;t4=yf4+hh*b4v;
                    float c0v,c1v,c2v,c3v,c4v;
                    RHS(t0,t1,t2,t3,t4,c0v,c1v,c2v,c3v,c4v);
                    t0=yf0+h*c0v;t1=yf1+h*c1v;t2=yf2+h*c2v;t3=yf3+h*c3v;t4=yf4+h*c4v;
                    float d0,d1,d2,d3,d4;
                    RHS(t0,t1,t2,t3,t4,d0,d1,d2,d3,d4);
#undef RHS
                    float s6 = h*(1.f/6.f);
                    yf0=fmaxf(yf0+s6*(a0+2.f*b0+2.f*c0v+d0),0.f);
                    yf1=fmaxf(yf1+s6*(a1+2.f*b1+2.f*c1v+d1),0.f);
                    yf2=fmaxf(yf2+s6*(a2+2.f*b2+2.f*c2v+d2),0.f);
                    yf3=fmaxf(yf3+s6*(a3+2.f*b3+2.f*c3v+d3),0.f);
                    yf4=fmaxf(yf4+s6*(a4+2.f*b4v+2.f*c4v+d4),0.f);
                    float* yo = out + ((size_t)bg*K + k)*3;
                    yo[0]=yf0; yo[1]=yf2; yo[2]=yf4;
                    sYobs[g*4+0]=yf0; sYobs[g*4+1]=yf2; sYobs[g*4+2]=yf4;
                    if (k+1 < K) {
                        sU[g*4+0]=nu0; sU[g*4+1]=nu1; sU[g*4+2]=nu2;
                        if (nflag) { sYtf[g*4+0]=nt0; sYtf[g*4+1]=nt1; sYtf[g*4+2]=nt2; }
                        cu0=nu0; cu1=nu1; cu2=nu2; cdt=ndt;
                    }
                }
            }
            asm volatile("bar.sync 1, 64;" ::: "memory");
            // ---- lift(k+1), 2 rows per thread ----
            {
                int kk1 = k + 1;
                bool lf = (kk1 % 50) == 0;
                const float* ub = sU + lbb*4;
                const float* yb = lf ? (sYtf + lbb*4) : (sYobs + lbb*4);
                float u0v=ub[0],u1v=ub[1],u2v=ub[2];
                float y0v=yb[0],y1v=yb[1],y2v=yb[2];
                float sA = blfA;
                sA=fmaf(wlA0,u0v,sA); sA=fmaf(wlA1,u1v,sA); sA=fmaf(wlA2,u2v,sA);
                sA=fmaf(wlA3,y0v,sA); sA=fmaf(wlA4,y1v,sA); sA=fmaf(wlA5,y2v,sA);
                sLift[lbb*LPIT + lr] = sA * sigm(sA);
                float sB = blfB;
                sB=fmaf(wlB0,u0v,sB); sB=fmaf(wlB1,u1v,sB); sB=fmaf(wlB2,u2v,sB);
                sB=fmaf(wlB3,y0v,sB); sB=fmaf(wlB4,y1v,sB); sB=fmaf(wlB5,y2v,sB);
                sLift[lbb*LPIT + 16 + lr] = sB * sigm(sB);
            }
        }
        __syncthreads();   // BAR_B: sLift(k+1) visible, gh(k+1) done
    }
}

extern "C" void kernel_launch(void* const* d_in, const int* in_sizes, int n_in,
                              void* d_out, int out_size)
{
    const float* y0     = (const float*)d_in[0];
    const float* u_seq  = (const float*)d_in[1];
    const float* dt_seq = (const float*)d_in[2];
    const float* y_seq  = (const float*)d_in[3];
    const float* W_lift = (const float*)d_in[4];
    const float* b_lift = (const float*)d_in[5];
    const float* W_ih   = (const float*)d_in[6];
    const float* W_hh   = (const float*)d_in[7];
    const float* b_ih   = (const float*)d_in[8];
    const float* b_hh   = (const float*)d_in[9];
    const float* W_head = (const float*)d_in[10];
    const float* b_head = (const float*)d_in[11];
    const float* u2y    = (const float*)d_in[12];
    float* out = (float*)d_out;

    int B = in_sizes[0] / 3;
    int K = in_sizes[2] / B;

    cudaFuncSetAttribute(krnn_kernel, cudaFuncAttributeMaxDynamicSharedMemorySize, SMEM_BYTES);
    krnn_kernel<<<B / 4, THREADS, SMEM_BYTES>>>(
        y0, u_seq, dt_seq, y_seq, W_lift, b_lift, W_ih, W_hh,
        b_ih, b_hh, W_head, b_head, u2y, out, B, K);
}

// round 14
// speedup vs baseline: 2.7348x; 2.7348x over previous
#include <cuda_runtime.h>
#include <math.h>

// KineticsRNN R14: R13 (576 threads, 4-way K-split) with the sH bank-conflict
// bug fixed: sH uses chunk-gapped layout (stride 36 == 4 mod 32), like W_hh.
// mat 512 threads: (i=t>>2, c=t&3) owns gate rows (r_i,z_i,n_i), K-quarter c;
// 2-round butterfly -> thread owns batch b=c; h_old in register.
// aux 64 threads: tail + lift overlapped with mat's gh.

#define THREADS 576
#define MATT 512
#define WPIT 144      // W_hh row pitch; chunk stride 36 (==4 mod 32)
#define WCH 36
#define HPIT 148      // sH row pitch (==20 mod 32); chunks at +36*c
#define HCH 36
#define HDPIT 132     // sWhd pitch
#define LPIT 36       // sLift pitch; chunk c at +8c (contiguous, conflict-free)

#define SMEM_FLOATS (384*WPIT + 4*HPIT + 4*LPIT + 5*HDPIT + 16 + 16 + 16)
#define SMEM_BYTES  (SMEM_FLOATS*4)

typedef unsigned long long u64;

__device__ __forceinline__ u64 fma2(u64 a, u64 b, u64 c) {
    u64 d;
    asm("fma.rn.f32x2 %0, %1, %2, %3;" : "=l"(d) : "l"(a), "l"(b), "l"(c));
    return d;
}
__device__ __forceinline__ float f2sum(u64 v) {
    float2 f;
    asm("mov.b64 {%0, %1}, %2;" : "=f"(f.x), "=f"(f.y) : "l"(v));
    return f.x + f.y;
}
__device__ __forceinline__ float sigm(float x) { return __fdividef(1.f, 1.f + __expf(-x)); }
__device__ __forceinline__ float tanh_f(float x) { return 1.f - __fdividef(2.f, __expf(2.f*x) + 1.f); }

__global__ __launch_bounds__(THREADS, 1)
void krnn_kernel(const float* __restrict__ y0,
                 const float* __restrict__ u_seq,
                 const float* __restrict__ dt_seq,
                 const float* __restrict__ y_seq,
                 const float* __restrict__ W_lift,
                 const float* __restrict__ b_lift,
                 const float* __restrict__ W_ih,
                 const float* __restrict__ W_hh,
                 const float* __restrict__ b_ih,
                 const float* __restrict__ b_hh,
                 const float* __restrict__ W_head,
                 const float* __restrict__ b_head,
                 const float* __restrict__ u2y,
                 float* __restrict__ out,
                 int B, int K)
{
    extern __shared__ float sm[];
    float* sWhh  = sm;                       // 384*144, chunk q at +36q
    float* sH    = sWhh + 384*WPIT;          // 4*148, chunk q at +36q
    float* sLift = sH + 4*HPIT;              // 4*36, chunk q at +8q
    float* sWhd  = sLift + 4*LPIT;           // 5*132 contiguous
    float* sU    = sWhd + 5*HDPIT;           // 4*4
    float* sYobs = sU + 16;
    float* sYtf  = sYobs + 16;

    const int t   = threadIdx.x;
    const int bg0 = blockIdx.x * 4;

    // ---- stage W_hh: word(row,kk) = row*144 + 36*(kk>>5) + (kk&31) ----
    {
        const float4* src = (const float4*)W_hh;
        for (int idx = t; idx < 384*32; idx += THREADS) {
            int row = idx >> 5, kb = idx & 31;
            int dst = row*WPIT + WCH*(kb >> 3) + 4*(kb & 7);
            *(float4*)(sWhh + dst) = src[idx];
        }
    }
    for (int idx = t; idx < 5*128; idx += THREADS)
        sWhd[(idx/128)*HDPIT + (idx%128)] = W_head[idx];

    // ================= mat state (512 threads) =================
    const int i = t >> 2, c = t & 3;
    u64 wihr[4], wihz[4], wihn[4];
    float cr = 0, cz = 0, bxn = 0, bhn = 0;
    float h_old = 0.f;
    if (t < MATT) {
        const ulonglong2* pr = (const ulonglong2*)(W_ih + (size_t)i*32 + 8*c);
        const ulonglong2* pz = (const ulonglong2*)(W_ih + (size_t)(128+i)*32 + 8*c);
        const ulonglong2* pn = (const ulonglong2*)(W_ih + (size_t)(256+i)*32 + 8*c);
#pragma unroll
        for (int j = 0; j < 2; j++) {
            ulonglong2 vr = pr[j]; wihr[2*j] = vr.x; wihr[2*j+1] = vr.y;
            ulonglong2 vz = pz[j]; wihz[2*j] = vz.x; wihz[2*j+1] = vz.y;
            ulonglong2 vn = pn[j]; wihn[2*j] = vn.x; wihn[2*j+1] = vn.y;
        }
        cr  = b_ih[i] + b_hh[i];
        cz  = b_ih[128+i] + b_hh[128+i];
        bxn = b_ih[256+i];
        bhn = b_hh[256+i];
    }
    const int hgi = HCH*(i >> 5) + (i & 31);  // gapped word of h_i within sH row

    // ================= aux state (64 threads, warps 16-17) =================
    const int g   = t - MATT;
    const int hbh = g / 5, hph = g % 5;
    const int lr  = g >> 2, lbb = g & 3;
    float bhd = 0.f;
    float wlA0=0,wlA1=0,wlA2=0,wlA3=0,wlA4=0,wlA5=0,blfA=0;
    float wlB0=0,wlB1=0,wlB2=0,wlB3=0,wlB4=0,wlB5=0,blfB=0;
    float yf0=0,yf1=0,yf2=0,yf3=0,yf4=0;
    float J00=0,J01=0,J02=0,J10=0,J11=0,J12=0,J20=0,J21=0,J22=0;
    float cu0=0,cu1=0,cu2=0,cdt=0;
    if (t >= MATT) {
        if (g < 20) bhd = b_head[hph];
        wlA0=W_lift[lr*6+0]; wlA1=W_lift[lr*6+1]; wlA2=W_lift[lr*6+2];
        wlA3=W_lift[lr*6+3]; wlA4=W_lift[lr*6+4]; wlA5=W_lift[lr*6+5];
        blfA=b_lift[lr];
        int lr2 = lr + 16;
        wlB0=W_lift[lr2*6+0]; wlB1=W_lift[lr2*6+1]; wlB2=W_lift[lr2*6+2];
        wlB3=W_lift[lr2*6+3]; wlB4=W_lift[lr2*6+4]; wlB5=W_lift[lr2*6+5];
        blfB=b_lift[lr2];
        if (g < 4) {
            int bg = bg0 + g;
            yf0 = y0[bg*3+0]; yf2 = y0[bg*3+1]; yf4 = y0[bg*3+2];
            J00=u2y[0];J01=u2y[1];J02=u2y[2];J10=u2y[3];J11=u2y[4];J12=u2y[5];
            J20=u2y[6];J21=u2y[7];J22=u2y[8];
            const float* up = u_seq + (size_t)bg*K*3;
            cu0=up[0]; cu1=up[1]; cu2=up[2];
            cdt = dt_seq[(size_t)bg*K];
            sU[g*4+0]=cu0; sU[g*4+1]=cu1; sU[g*4+2]=cu2;
            sYobs[g*4+0]=yf0; sYobs[g*4+1]=yf2; sYobs[g*4+2]=yf4;
        }
    }
    for (int idx = t; idx < 4*HPIT; idx += THREADS) sH[idx] = 0.f;
    __syncthreads();

    // ---- prologue: lift(0) ----
    if (t >= MATT) {
        const float* ub = sU + lbb*4;
        const float* yb = sYobs + lbb*4;
        float sA = blfA;
        sA=fmaf(wlA0,ub[0],sA); sA=fmaf(wlA1,ub[1],sA); sA=fmaf(wlA2,ub[2],sA);
        sA=fmaf(wlA3,yb[0],sA); sA=fmaf(wlA4,yb[1],sA); sA=fmaf(wlA5,yb[2],sA);
        sLift[lbb*LPIT + lr] = sA * sigm(sA);
        float sB = blfB;
        sB=fmaf(wlB0,ub[0],sB); sB=fmaf(wlB1,ub[1],sB); sB=fmaf(wlB2,ub[2],sB);
        sB=fmaf(wlB3,yb[0],sB); sB=fmaf(wlB4,yb[1],sB); sB=fmaf(wlB5,yb[2],sB);
        sLift[lbb*LPIT + 16 + lr] = sB * sigm(sB);
    }
    __syncthreads();

    const size_t thb = (size_t)B*K*3;
    const int c0 = c & 1, c1 = c >> 1;

    u64 aR0=0,aR1=0,aR2=0,aR3=0, aZ0=0,aZ1=0,aZ2=0,aZ3=0, aN0=0,aN1=0,aN2=0,aN3=0;
    float nu0=0,nu1=0,nu2=0,ndt=0,nt0=0,nt1=0,nt2=0;
    bool nflag = false;

    for (int k = 0; k < K; k++) {
        if (t < MATT) {
            // ---- P1: gx(k) ----
            u64 aX0=0,aX1=0,aX2=0,aX3=0;
            {
                const ulonglong2* l0 = (const ulonglong2*)(sLift + 0*LPIT + 8*c);
                const ulonglong2* l1 = (const ulonglong2*)(sLift + 1*LPIT + 8*c);
                const ulonglong2* l2 = (const ulonglong2*)(sLift + 2*LPIT + 8*c);
                const ulonglong2* l3 = (const ulonglong2*)(sLift + 3*LPIT + 8*c);
#pragma unroll
                for (int j = 0; j < 2; j++) {
                    u64 wa=wihr[2*j], wb=wihr[2*j+1];
                    u64 za=wihz[2*j], zb=wihz[2*j+1];
                    u64 na=wihn[2*j], nb=wihn[2*j+1];
                    ulonglong2 v0=l0[j];
                    aR0=fma2(wa,v0.x,aR0); aR0=fma2(wb,v0.y,aR0);
                    aZ0=fma2(za,v0.x,aZ0); aZ0=fma2(zb,v0.y,aZ0);
                    aX0=fma2(na,v0.x,aX0); aX0=fma2(nb,v0.y,aX0);
                    ulonglong2 v1=l1[j];
                    aR1=fma2(wa,v1.x,aR1); aR1=fma2(wb,v1.y,aR1);
                    aZ1=fma2(za,v1.x,aZ1); aZ1=fma2(zb,v1.y,aZ1);
                    aX1=fma2(na,v1.x,aX1); aX1=fma2(nb,v1.y,aX1);
                    ulonglong2 v2=l2[j];
                    aR2=fma2(wa,v2.x,aR2); aR2=fma2(wb,v2.y,aR2);
                    aZ2=fma2(za,v2.x,aZ2); aZ2=fma2(zb,v2.y,aZ2);
                    aX2=fma2(na,v2.x,aX2); aX2=fma2(nb,v2.y,aX2);
                    ulonglong2 v3=l3[j];
                    aR3=fma2(wa,v3.x,aR3); aR3=fma2(wb,v3.y,aR3);
                    aZ3=fma2(za,v3.x,aZ3); aZ3=fma2(zb,v3.y,aZ3);
                    aX3=fma2(na,v3.x,aX3); aX3=fma2(nb,v3.y,aX3);
                }
            }
            // ---- 2-round butterfly -> totals for batch b=c ----
            float pR0=f2sum(aR0),pR1=f2sum(aR1),pR2=f2sum(aR2),pR3=f2sum(aR3);
            float pZ0=f2sum(aZ0),pZ1=f2sum(aZ1),pZ2=f2sum(aZ2),pZ3=f2sum(aZ3);
            float pN0=f2sum(aN0),pN1=f2sum(aN1),pN2=f2sum(aN2),pN3=f2sum(aN3);
            float pX0=f2sum(aX0),pX1=f2sum(aX1),pX2=f2sum(aX2),pX3=f2sum(aX3);
            float tR0 = (c0?pR1:pR0) + __shfl_xor_sync(0xffffffffu, c0?pR0:pR1, 1);
            float tR2 = (c0?pR3:pR2) + __shfl_xor_sync(0xffffffffu, c0?pR2:pR3, 1);
            float tZ0 = (c0?pZ1:pZ0) + __shfl_xor_sync(0xffffffffu, c0?pZ0:pZ1, 1);
            float tZ2 = (c0?pZ3:pZ2) + __shfl_xor_sync(0xffffffffu, c0?pZ2:pZ3, 1);
            float tN0 = (c0?pN1:pN0) + __shfl_xor_sync(0xffffffffu, c0?pN0:pN1, 1);
            float tN2 = (c0?pN3:pN2) + __shfl_xor_sync(0xffffffffu, c0?pN2:pN3, 1);
            float tX0 = (c0?pX1:pX0) + __shfl_xor_sync(0xffffffffu, c0?pX0:pX1, 1);
            float tX2 = (c0?pX3:pX2) + __shfl_xor_sync(0xffffffffu, c0?pX2:pX3, 1);
            float TR = (c1?tR2:tR0) + __shfl_xor_sync(0xffffffffu, c1?tR0:tR2, 2);
            float TZ = (c1?tZ2:tZ0) + __shfl_xor_sync(0xffffffffu, c1?tZ0:tZ2, 2);
            float TN = (c1?tN2:tN0) + __shfl_xor_sync(0xffffffffu, c1?tN0:tN2, 2);
            float TX = (c1?tX2:tX0) + __shfl_xor_sync(0xffffffffu, c1?tX0:tX2, 2);
            // ---- P2: gates + h for batch c ----
            {
                float r = sigm(TR + cr);
                float z = sigm(TZ + cz);
                float n = tanh_f(TX + bxn + r*(TN + bhn));
                h_old = n + z*(h_old - n);
                sH[c*HPIT + hgi] = h_old;
            }
            aR0=aR1=aR2=aR3=0; aZ0=aZ1=aZ2=aZ3=0; aN0=aN1=aN2=aN3=0;
        } else {
            nflag = false;
            if (g < 4 && (k+1) < K) {
                int bg = bg0 + g;
                const float* up = u_seq + ((size_t)bg*K + (k+1))*3;
                nu0=up[0]; nu1=up[1]; nu2=up[2];
                ndt = dt_seq[(size_t)bg*K + (k+1)];
                nflag = ((k+1) % 50) == 0;
                if (nflag) {
                    const float* yp = y_seq + ((size_t)bg*K + k)*3;
                    nt0=yp[0]; nt1=yp[1]; nt2=yp[2];
                }
            }
        }
        __syncthreads();   // BAR_A: sH = h(k) visible

        if (t < MATT) {
            // ---- gh(k+1) = W_hh @ h(k), K-quarter c, 4 batches ----
            const ulonglong2* wR = (const ulonglong2*)(sWhh + i*WPIT + WCH*c);
            const ulonglong2* wZ = (const ulonglong2*)(sWhh + (128+i)*WPIT + WCH*c);
            const ulonglong2* wN = (const ulonglong2*)(sWhh + (256+i)*WPIT + WCH*c);
            const ulonglong2* x0 = (const ulonglong2*)(sH + 0*HPIT + HCH*c);
            const ulonglong2* x1 = (const ulonglong2*)(sH + 1*HPIT + HCH*c);
            const ulonglong2* x2 = (const ulonglong2*)(sH + 2*HPIT + HCH*c);
            const ulonglong2* x3 = (const ulonglong2*)(sH + 3*HPIT + HCH*c);
#pragma unroll
            for (int j = 0; j < 8; j++) {
                ulonglong2 wr=wR[j], wz=wZ[j], wn=wN[j];
                ulonglong2 v0=x0[j];
                aR0=fma2(wr.x,v0.x,aR0); aR0=fma2(wr.y,v0.y,aR0);
                aZ0=fma2(wz.x,v0.x,aZ0); aZ0=fma2(wz.y,v0.y,aZ0);
                aN0=fma2(wn.x,v0.x,aN0); aN0=fma2(wn.y,v0.y,aN0);
                ulonglong2 v1=x1[j];
                aR1=fma2(wr.x,v1.x,aR1); aR1=fma2(wr.y,v1.y,aR1);
                aZ1=fma2(wz.x,v1.x,aZ1); aZ1=fma2(wz.y,v1.y,aZ1);
                aN1=fma2(wn.x,v1.x,aN1); aN1=fma2(wn.y,v1.y,aN1);
                ulonglong2 v2=x2[j];
                aR2=fma2(wr.x,v2.x,aR2); aR2=fma2(wr.y,v2.y,aR2);
                aZ2=fma2(wz.x,v2.x,aZ2); aZ2=fma2(wz.y,v2.y,aZ2);
                aN2=fma2(wn.x,v2.x,aN2); aN2=fma2(wn.y,v2.y,aN2);
                ulonglong2 v3=x3[j];
                aR3=fma2(wr.x,v3.x,aR3); aR3=fma2(wr.y,v3.y,aR3);
                aZ3=fma2(wz.x,v3.x,aZ3); aZ3=fma2(wz.y,v3.y,aZ3);
                aN3=fma2(wn.x,v3.x,aN3); aN3=fma2(wn.y,v3.y,aN3);
            }
        } else {
            // ---- tail(k): head + theta + RK4 + outputs ----
            float thv = 0.f;
            if (g < 20) {
                u64 s0 = 0, s1 = 0;
#pragma unroll
                for (int ch = 0; ch < 4; ch++) {
                    const ulonglong2* hr = (const ulonglong2*)(sH + hbh*HPIT + HCH*ch);
                    const ulonglong2* wp = (const ulonglong2*)(sWhd + hph*HDPIT + 32*ch);
#pragma unroll
                    for (int jb = 0; jb < 8; jb++) {
                        ulonglong2 h4 = hr[jb];
                        ulonglong2 w4 = wp[jb];
                        s0 = fma2(w4.x, h4.x, s0);
                        s1 = fma2(w4.y, h4.y, s1);
                    }
                }
                float s = f2sum(s0) + f2sum(s1) + bhd;
                thv = 0.001f + 1.999f * sigm(s);
                out[thb + ((size_t)(bg0 + hbh)*K + k)*5 + hph] = thv;
            }
            if (g < 32) {   // warp 16 only
                float th0 = __shfl_sync(0xffffffffu, thv, g*5+0);
                float th1 = __shfl_sync(0xffffffffu, thv, g*5+1);
                float th2 = __shfl_sync(0xffffffffu, thv, g*5+2);
                float th3 = __shfl_sync(0xffffffffu, thv, g*5+3);
                float th4 = __shfl_sync(0xffffffffu, thv, g*5+4);
                if (g < 4) {
                    int bg = bg0 + g;
                    yf0 += cu0*J00 + cu1*J10 + cu2*J20;
                    yf2 += cu0*J01 + cu1*J11 + cu2*J21;
                    yf4 += cu0*J02 + cu1*J12 + cu2*J22;
                    float h = cdt, hh = 0.5f*h;
#define RHS(A_,Bv,C_,D_,E_,d0,d1,d2,d3,d4) { \
    float r1=th0*(A_)*(Bv); float r2=th1*(C_); float r3=th2*(C_)*(D_); \
    float r4=th3*(E_); float r5=th4*(A_); \
    d0=-r1-r5; d1=-r1+r2; d2=r1-r2-r3; d3=-r3+r4; d4=r3-r4+r5; }
                    float a0,a1,a2,a3,a4;
                    RHS(yf0,yf1,yf2,yf3,yf4,a0,a1,a2,a3,a4);
                    float t0=yf0+hh*a0,t1=yf1+hh*a1,t2=yf2+hh*a2,t3=yf3+hh*a3,t4=yf4+hh*a4;
                    float b0,b1,b2,b3,b4v;
                    RHS(t0,t1,t2,t3,t4,b0,b1,b2,b3,b4v);
                    t0=yf0+hh*b0;t1=yf1+hh*b1;t2=yf2+hh*b2;t3=yf3+hh*b3;t4=yf4+hh*b4v;
                    float c0v,c1v,c2v,c3v,c4v;
                    RHS(t0,t1,t2,t3,t4,c0v,c1v,c2v,c3v,c4v);
                    t0=yf0+h*c0v;t1=yf1+h*c1v;t2=yf2+h*c2v;t3=yf3+h*c3v;t4=yf4+h*c4v;
                    float d0,d1,d2,d3,d4;
                    RHS(t0,t1,t2,t3,t4,d0,d1,d2,d3,d4);
#undef RHS
                    float s6 = h*(1.f/6.f);
                    yf0=fmaxf(yf0+s6*(a0+2.f*b0+2.f*c0v+d0),0.f);
                    yf1=fmaxf(yf1+s6*(a1+2.f*b1+2.f*c1v+d1),0.f);
                    yf2=fmaxf(yf2+s6*(a2+2.f*b2+2.f*c2v+d2),0.f);
                    yf3=fmaxf(yf3+s6*(a3+2.f*b3+2.f*c3v+d3),0.f);
                    yf4=fmaxf(yf4+s6*(a4+2.f*b4v+2.f*c4v+d4),0.f);
                    float* yo = out + ((size_t)bg*K + k)*3;
                    yo[0]=yf0; yo[1]=yf2; yo[2]=yf4;
                    sYobs[g*4+0]=yf0; sYobs[g*4+1]=yf2; sYobs[g*4+2]=yf4;
                    if (k+1 < K) {
                        sU[g*4+0]=nu0; sU[g*4+1]=nu1; sU[g*4+2]=nu2;
                        if (nflag) { sYtf[g*4+0]=nt0; sYtf[g*4+1]=nt1; sYtf[g*4+2]=nt2; }
                        cu0=nu0; cu1=nu1; cu2=nu2; cdt=ndt;
                    }
                }
            }
            asm volatile("bar.sync 1, 64;" ::: "memory");
            // ---- lift(k+1), 2 rows per thread ----
            {
                int kk1 = k + 1;
                bool lf = (kk1 % 50) == 0;
                const float* ub = sU + lbb*4;
                const float* yb = lf ? (sYtf + lbb*4) : (sYobs + lbb*4);
                float u0v=ub[0],u1v=ub[1],u2v=ub[2];
                float y0v=yb[0],y1v=yb[1],y2v=yb[2];
                float sA = blfA;
                sA=fmaf(wlA0,u0v,sA); sA=fmaf(wlA1,u1v,sA); sA=fmaf(wlA2,u2v,sA);
                sA=fmaf(wlA3,y0v,sA); sA=fmaf(wlA4,y1v,sA); sA=fmaf(wlA5,y2v,sA);
                sLift[lbb*LPIT + lr] = sA * sigm(sA);
                float sB = blfB;
                sB=fmaf(wlB0,u0v,sB); sB=fmaf(wlB1,u1v,sB); sB=fmaf(wlB2,u2v,sB);
                sB=fmaf(wlB3,y0v,sB); sB=fmaf(wlB4,y1v,sB); sB=fmaf(wlB5,y2v,sB);
                sLift[lbb*LPIT + 16 + lr] = sB * sigm(sB);
            }
        }
        __syncthreads();   // BAR_B
    }
}

extern "C" void kernel_launch(void* const* d_in, const int* in_sizes, int n_in,
                              void* d_out, int out_size)
{
    const float* y0     = (const float*)d_in[0];
    const float* u_seq  = (const float*)d_in[1];
    const float* dt_seq = (const float*)d_in[2];
    const float* y_seq  = (const float*)d_in[3];
    const float* W_lift = (const float*)d_in[4];
    const float* b_lift = (const float*)d_in[5];
    const float* W_ih   = (const float*)d_in[6];
    const float* W_hh   = (const float*)d_in[7];
    const float* b_ih   = (const float*)d_in[8];
    const float* b_hh   = (const float*)d_in[9];
    const float* W_head = (const float*)d_in[10];
    const float* b_head = (const float*)d_in[11];
    const float* u2y    = (const float*)d_in[12];
    float* out = (float*)d_out;

    int B = in_sizes[0] / 3;
    int K = in_sizes[2] / B;

    cudaFuncSetAttribute(krnn_kernel, cudaFuncAttributeMaxDynamicSharedMemorySize, SMEM_BYTES);
    krnn_kernel<<<B / 4, THREADS, SMEM_BYTES>>>(
        y0, u_seq, dt_seq, y_seq, W_lift, b_lift, W_ih, W_hh,
        b_ih, b_hh, W_head, b_head, u2y, out, B, K);
}

// round 15
// speedup vs baseline: 2.8093x; 1.0273x over previous
#include <cuda_runtime.h>
#include <math.h>

// KineticsRNN R15: exact R5 structure (best: 1142.8us) with one change:
// P1's 16-shfl butterfly replaced by the 8-shfl exchange (R7-verified logic).
// 256 mat threads: (i=t>>1, c=t&1) own gate rows (r_i,z_i,n_i), K-half c.
// 128 aux threads: tail (head+RK4+outputs) overlapped with mat's gh; lift.

#define THREADS 384
#define MATT 256
#define HDIM 128
#define PITCH 136     // W_hh / sH / sWhd pitch (words); K-chunk1 at +68
#define CGAP 68
#define LPITCH 40     // sLift pitch; chunk1 at +20
#define LGAP 20

#define SMEM_FLOATS (384*PITCH + 4*PITCH + 4*LPITCH + 5*PITCH + 16 + 16 + 16)
#define SMEM_BYTES  (SMEM_FLOATS * 4)

typedef unsigned long long u64;

__device__ __forceinline__ u64 fma2(u64 a, u64 b, u64 c) {
    u64 d;
    asm("fma.rn.f32x2 %0, %1, %2, %3;" : "=l"(d) : "l"(a), "l"(b), "l"(c));
    return d;
}
__device__ __forceinline__ float f2sum(u64 v) {
    float2 f;
    asm("mov.b64 {%0, %1}, %2;" : "=f"(f.x), "=f"(f.y) : "l"(v));
    return f.x + f.y;
}
__device__ __forceinline__ float sigm(float x) {
    return __fdividef(1.0f, 1.0f + __expf(-x));
}
__device__ __forceinline__ float tanh_f(float x) {
    return 1.0f - __fdividef(2.0f, __expf(2.0f * x) + 1.0f);
}

__global__ __launch_bounds__(THREADS, 1)
void krnn_kernel(const float* __restrict__ y0,
                 const float* __restrict__ u_seq,
                 const float* __restrict__ dt_seq,
                 const float* __restrict__ y_seq,
                 const float* __restrict__ W_lift,
                 const float* __restrict__ b_lift,
                 const float* __restrict__ W_ih,
                 const float* __restrict__ W_hh,
                 const float* __restrict__ b_ih,
                 const float* __restrict__ b_hh,
                 const float* __restrict__ W_head,
                 const float* __restrict__ b_head,
                 const float* __restrict__ u2y,
                 float* __restrict__ out,
                 int B, int K)
{
    extern __shared__ float sm[];
    float* sWhh  = sm;                       // 384*136 (gapped rows)
    float* sH    = sWhh + 384 * PITCH;       // 4*136 (gapped)
    float* sLift = sH + 4 * PITCH;           // 4*40 (gapped)
    float* sWhd  = sLift + 4 * LPITCH;       // 5*136
    float* sU    = sWhd + 5 * PITCH;         // 4*4
    float* sYobs = sU + 16;                  // 4*4
    float* sYtf  = sYobs + 16;               // 4*4

    const int t   = threadIdx.x;
    const int bg0 = blockIdx.x * 4;

    // ---- stage W_hh gapped: word(row,k) = row*136 + k + 4*(k>=64) ----
    {
        const float4* src = (const float4*)W_hh;
        for (int idx = t; idx < 384 * 32; idx += THREADS) {
            int row = idx >> 5, kb = idx & 31;
            int dst = row * PITCH + 4 * kb + ((kb >> 4) << 2);
            *(float4*)(sWhh + dst) = src[idx];
        }
    }
    for (int idx = t; idx < 5 * HDIM; idx += THREADS)
        sWhd[(idx / HDIM) * PITCH + (idx % HDIM)] = W_head[idx];

    // ================= mat-thread persistent state =================
    const int i = t >> 1, c = t & 1;
    u64 wr_[8], wz_[8], wn_[8];
    float cr = 0, cz = 0, bxn = 0, bhn = 0;
    if (t < MATT) {
        const ulonglong2* pr = (const ulonglong2*)(W_ih + (size_t)i * 32 + 16 * c);
        const ulonglong2* pz = (const ulonglong2*)(W_ih + (size_t)(128 + i) * 32 + 16 * c);
        const ulonglong2* pn = (const ulonglong2*)(W_ih + (size_t)(256 + i) * 32 + 16 * c);
#pragma unroll
        for (int j = 0; j < 4; j++) {
            ulonglong2 vr = pr[j]; wr_[2 * j] = vr.x; wr_[2 * j + 1] = vr.y;
            ulonglong2 vz = pz[j]; wz_[2 * j] = vz.x; wz_[2 * j + 1] = vz.y;
            ulonglong2 vn = pn[j]; wn_[2 * j] = vn.x; wn_[2 * j + 1] = vn.y;
        }
        cr  = b_ih[i] + b_hh[i];
        cz  = b_ih[128 + i] + b_hh[128 + i];
        bxn = b_ih[256 + i];
        bhn = b_hh[256 + i];
    }

    // ================= aux-thread persistent state =================
    const int g   = t - 256;                  // aux index (valid t>=256)
    const int hbh = g / 5, hph = g % 5;       // head map (g<20)
    const int lr  = g >> 2, lbb = g & 3;      // lift map
    const int lgl = lr + ((lr >> 4) << 2);
    float bhd = 0.f;
    float wl0 = 0, wl1 = 0, wl2 = 0, wl3 = 0, wl4 = 0, wl5 = 0, blf = 0;
    float yf0 = 0, yf1 = 0, yf2 = 0, yf3 = 0, yf4 = 0;
    float J00 = 0, J01 = 0, J02 = 0, J10 = 0, J11 = 0, J12 = 0, J20 = 0, J21 = 0, J22 = 0;
    float cu0 = 0, cu1 = 0, cu2 = 0, cdt = 0;
    if (t >= MATT) {
        if (g < 20) bhd = b_head[hph];
        wl0 = W_lift[lr * 6 + 0]; wl1 = W_lift[lr * 6 + 1]; wl2 = W_lift[lr * 6 + 2];
        wl3 = W_lift[lr * 6 + 3]; wl4 = W_lift[lr * 6 + 4]; wl5 = W_lift[lr * 6 + 5];
        blf = b_lift[lr];
        if (g < 4) {
            int bg = bg0 + g;
            yf0 = y0[bg * 3 + 0]; yf2 = y0[bg * 3 + 1]; yf4 = y0[bg * 3 + 2];
            J00 = u2y[0]; J01 = u2y[1]; J02 = u2y[2];
            J10 = u2y[3]; J11 = u2y[4]; J12 = u2y[5];
            J20 = u2y[6]; J21 = u2y[7]; J22 = u2y[8];
            const float* up = u_seq + (size_t)bg * K * 3;
            cu0 = up[0]; cu1 = up[1]; cu2 = up[2];
            cdt = dt_seq[(size_t)bg * K];
            sU[g * 4 + 0] = cu0; sU[g * 4 + 1] = cu1; sU[g * 4 + 2] = cu2;
            sYobs[g * 4 + 0] = yf0; sYobs[g * 4 + 1] = yf2; sYobs[g * 4 + 2] = yf4;
        }
    }
    for (int idx = t; idx < 4 * PITCH; idx += THREADS) sH[idx] = 0.f;
    __syncthreads();

    // ---- prologue: lift(0) ----
    if (t >= MATT) {
        const float* ub = sU + lbb * 4;
        const float* yb = sYobs + lbb * 4;
        float s = blf;
        s = fmaf(wl0, ub[0], s); s = fmaf(wl1, ub[1], s); s = fmaf(wl2, ub[2], s);
        s = fmaf(wl3, yb[0], s); s = fmaf(wl4, yb[1], s); s = fmaf(wl5, yb[2], s);
        sLift[lbb * LPITCH + lgl] = s * sigm(s);
    }
    __syncthreads();

    const size_t theta_base = (size_t)B * K * 3;

    // gh accumulators (zero => gh(0) = 0)
    u64 aR0 = 0, aR1 = 0, aR2 = 0, aR3 = 0;
    u64 aZ0 = 0, aZ1 = 0, aZ2 = 0, aZ3 = 0;
    u64 aN0 = 0, aN1 = 0, aN2 = 0, aN3 = 0;   // ghn
    float nu0 = 0, nu1 = 0, nu2 = 0, ndt = 0, nt0 = 0, nt1 = 0, nt2 = 0;
    bool nflag = false;

    for (int k = 0; k < K; k++) {
        if (t < MATT) {
            // ---- P1: gx(k) (r,z merge into aR/aZ; n part separate) ----
            u64 aX0 = 0, aX1 = 0, aX2 = 0, aX3 = 0;
            {
                const ulonglong2* l0 = (const ulonglong2*)(sLift + 0 * LPITCH + LGAP * c);
                const ulonglong2* l1 = (const ulonglong2*)(sLift + 1 * LPITCH + LGAP * c);
                const ulonglong2* l2 = (const ulonglong2*)(sLift + 2 * LPITCH + LGAP * c);
                const ulonglong2* l3 = (const ulonglong2*)(sLift + 3 * LPITCH + LGAP * c);
#pragma unroll
                for (int j = 0; j < 4; j++) {
                    u64 wa = wr_[2 * j], wb = wr_[2 * j + 1];
                    u64 za = wz_[2 * j], zb = wz_[2 * j + 1];
                    u64 na = wn_[2 * j], nb = wn_[2 * j + 1];
                    ulonglong2 v0 = l0[j];
                    aR0 = fma2(wa, v0.x, aR0); aR0 = fma2(wb, v0.y, aR0);
                    aZ0 = fma2(za, v0.x, aZ0); aZ0 = fma2(zb, v0.y, aZ0);
                    aX0 = fma2(na, v0.x, aX0); aX0 = fma2(nb, v0.y, aX0);
                    ulonglong2 v1 = l1[j];
                    aR1 = fma2(wa, v1.x, aR1); aR1 = fma2(wb, v1.y, aR1);
                    aZ1 = fma2(za, v1.x, aZ1); aZ1 = fma2(zb, v1.y, aZ1);
                    aX1 = fma2(na, v1.x, aX1); aX1 = fma2(nb, v1.y, aX1);
                    ulonglong2 v2 = l2[j];
                    aR2 = fma2(wa, v2.x, aR2); aR2 = fma2(wb, v2.y, aR2);
                    aZ2 = fma2(za, v2.x, aZ2); aZ2 = fma2(zb, v2.y, aZ2);
                    aX2 = fma2(na, v2.x, aX2); aX2 = fma2(nb, v2.y, aX2);
                    ulonglong2 v3 = l3[j];
                    aR3 = fma2(wa, v3.x, aR3); aR3 = fma2(wb, v3.y, aR3);
                    aZ3 = fma2(za, v3.x, aZ3); aZ3 = fma2(zb, v3.y, aZ3);
                    aX3 = fma2(na, v3.x, aX3); aX3 = fma2(nb, v3.y, aX3);
                }
            }
            // ---- 8-shfl exchange: totals for this lane's 2 batches ----
            float pR0 = f2sum(aR0), pR1 = f2sum(aR1), pR2 = f2sum(aR2), pR3 = f2sum(aR3);
            float pZ0 = f2sum(aZ0), pZ1 = f2sum(aZ1), pZ2 = f2sum(aZ2), pZ3 = f2sum(aZ3);
            float pN0 = f2sum(aN0), pN1 = f2sum(aN1), pN2 = f2sum(aN2), pN3 = f2sum(aN3);
            float pX0 = f2sum(aX0), pX1 = f2sum(aX1), pX2 = f2sum(aX2), pX3 = f2sum(aX3);
            float vRA = c ? pR0 : pR2, vRB = c ? pR1 : pR3;
            float vZA = c ? pZ0 : pZ2, vZB = c ? pZ1 : pZ3;
            float vNA = c ? pN0 : pN2, vNB = c ? pN1 : pN3;
            float vXA = c ? pX0 : pX2, vXB = c ? pX1 : pX3;
            float totRA = (c ? pR2 : pR0) + __shfl_xor_sync(0xffffffffu, vRA, 1);
            float totRB = (c ? pR3 : pR1) + __shfl_xor_sync(0xffffffffu, vRB, 1);
            float totZA = (c ? pZ2 : pZ0) + __shfl_xor_sync(0xffffffffu, vZA, 1);
            float totZB = (c ? pZ3 : pZ1) + __shfl_xor_sync(0xffffffffu, vZB, 1);
            float totNA = (c ? pN2 : pN0) + __shfl_xor_sync(0xffffffffu, vNA, 1);
            float totNB = (c ? pN3 : pN1) + __shfl_xor_sync(0xffffffffu, vNB, 1);
            float totXA = (c ? pX2 : pX0) + __shfl_xor_sync(0xffffffffu, vXA, 1);
            float totXB = (c ? pX3 : pX1) + __shfl_xor_sync(0xffffffffu, vXB, 1);
            const int bA = 2 * c, bB = 2 * c + 1;
            const int gi = i + ((i >> 6) << 2);
            {
                float r = sigm(totRA + cr);
                float z = sigm(totZA + cz);
                float n = tanh_f(totXA + bxn + r * (totNA + bhn));
                float ho = sH[bA * PITCH + gi];
                sH[bA * PITCH + gi] = n + z * (ho - n);
            }
            {
                float r = sigm(totRB + cr);
                float z = sigm(totZB + cz);
                float n = tanh_f(totXB + bxn + r * (totNB + bhn));
                float ho = sH[bB * PITCH + gi];
                sH[bB * PITCH + gi] = n + z * (ho - n);
            }
            aR0 = aR1 = aR2 = aR3 = 0;
            aZ0 = aZ1 = aZ2 = aZ3 = 0;
            aN0 = aN1 = aN2 = aN3 = 0;
        } else {
            // ---- prefetch step-(k+1) inputs ----
            nflag = false;
            if (g < 4 && (k + 1) < K) {
                int bg = bg0 + g;
                const float* up = u_seq + ((size_t)bg * K + (k + 1)) * 3;
                nu0 = up[0]; nu1 = up[1]; nu2 = up[2];
                ndt = dt_seq[(size_t)bg * K + (k + 1)];
                nflag = ((k + 1) % 50) == 0;
                if (nflag) {
                    const float* yp = y_seq + ((size_t)bg * K + k) * 3;
                    nt0 = yp[0]; nt1 = yp[1]; nt2 = yp[2];
                }
            }
        }
        __syncthreads();   // BAR_A: sH = h(k) visible

        if (t < MATT) {
            // ---- gh(k+1) = W_hh @ h(k), overlapped with aux tail ----
            const ulonglong2* wRp = (const ulonglong2*)(sWhh + i * PITCH + CGAP * c);
            const ulonglong2* wZp = (const ulonglong2*)(sWhh + (128 + i) * PITCH + CGAP * c);
            const ulonglong2* wNp = (const ulonglong2*)(sWhh + (256 + i) * PITCH + CGAP * c);
            const ulonglong2* x0 = (const ulonglong2*)(sH + 0 * PITCH + CGAP * c);
            const ulonglong2* x1 = (const ulonglong2*)(sH + 1 * PITCH + CGAP * c);
            const ulonglong2* x2 = (const ulonglong2*)(sH + 2 * PITCH + CGAP * c);
            const ulonglong2* x3 = (const ulonglong2*)(sH + 3 * PITCH + CGAP * c);
#pragma unroll
            for (int j = 0; j < 16; j++) {
                ulonglong2 wR = wRp[j], wZ = wZp[j], wN = wNp[j];
                ulonglong2 v0 = x0[j];
                aR0 = fma2(wR.x, v0.x, aR0); aR0 = fma2(wR.y, v0.y, aR0);
                aZ0 = fma2(wZ.x, v0.x, aZ0); aZ0 = fma2(wZ.y, v0.y, aZ0);
                aN0 = fma2(wN.x, v0.x, aN0); aN0 = fma2(wN.y, v0.y, aN0);
                ulonglong2 v1 = x1[j];
                aR1 = fma2(wR.x, v1.x, aR1); aR1 = fma2(wR.y, v1.y, aR1);
                aZ1 = fma2(wZ.x, v1.x, aZ1); aZ1 = fma2(wZ.y, v1.y, aZ1);
                aN1 = fma2(wN.x, v1.x, aN1); aN1 = fma2(wN.y, v1.y, aN1);
                ulonglong2 v2 = x2[j];
                aR2 = fma2(wR.x, v2.x, aR2); aR2 = fma2(wR.y, v2.y, aR2);
                aZ2 = fma2(wZ.x, v2.x, aZ2); aZ2 = fma2(wZ.y, v2.y, aZ2);
                aN2 = fma2(wN.x, v2.x, aN2); aN2 = fma2(wN.y, v2.y, aN2);
                ulonglong2 v3 = x3[j];
                aR3 = fma2(wR.x, v3.x, aR3); aR3 = fma2(wR.y, v3.y, aR3);
                aZ3 = fma2(wZ.x, v3.x, aZ3); aZ3 = fma2(wZ.y, v3.y, aZ3);
                aN3 = fma2(wN.x, v3.x, aN3); aN3 = fma2(wN.y, v3.y, aN3);
            }
        } else {
            // ---- tail(k): head + theta + RK4 + outputs ----
            float thv = 0.f;
            if (g < 20) {
                u64 s0 = 0, s1 = 0;
#pragma unroll
                for (int half = 0; half < 2; half++) {
                    const ulonglong2* hr = (const ulonglong2*)(sH + hbh * PITCH + CGAP * half);
                    const ulonglong2* wp = (const ulonglong2*)(sWhd + hph * PITCH + 64 * half);
#pragma unroll
                    for (int jb = 0; jb < 16; jb++) {
                        ulonglong2 h4 = hr[jb];
                        ulonglong2 w4 = wp[jb];
                        s0 = fma2(w4.x, h4.x, s0);
                        s1 = fma2(w4.y, h4.y, s1);
                    }
                }
                float s = f2sum(s0) + f2sum(s1) + bhd;
                thv = 0.001f + 1.999f * sigm(s);
                out[theta_base + ((size_t)(bg0 + hbh) * K + k) * 5 + hph] = thv;
            }
            if (g < 32) {   // warp 8 only (uniform)
                float th0 = __shfl_sync(0xffffffffu, thv, g * 5 + 0);
                float th1 = __shfl_sync(0xffffffffu, thv, g * 5 + 1);
                float th2 = __shfl_sync(0xffffffffu, thv, g * 5 + 2);
                float th3 = __shfl_sync(0xffffffffu, thv, g * 5 + 3);
                float th4 = __shfl_sync(0xffffffffu, thv, g * 5 + 4);
                if (g < 4) {
                    yf0 += cu0 * J00 + cu1 * J10 + cu2 * J20;
                    yf2 += cu0 * J01 + cu1 * J11 + cu2 * J21;
                    yf4 += cu0 * J02 + cu1 * J12 + cu2 * J22;
                    float h  = cdt;
                    float hhf = 0.5f * h;
#define RHS(A_, Bv, C_, D_, E_, d0, d1, d2, d3, d4)                      \
                    {                                                    \
                        float r1 = th0 * (A_) * (Bv);                    \
                        float r2 = th1 * (C_);                           \
                        float r3 = th2 * (C_) * (D_);                    \
                        float r4 = th3 * (E_);                           \
                        float r5 = th4 * (A_);                           \
                        d0 = -r1 - r5; d1 = -r1 + r2; d2 = r1 - r2 - r3; \
                        d3 = -r3 + r4; d4 = r3 - r4 + r5;                \
                    }
                    float a0, a1, a2, a3, a4;
                    RHS(yf0, yf1, yf2, yf3, yf4, a0, a1, a2, a3, a4);
                    float t0 = yf0 + hhf * a0, t1 = yf1 + hhf * a1, t2 = yf2 + hhf * a2,
                          t3 = yf3 + hhf * a3, t4 = yf4 + hhf * a4;
                    float b0, b1, b2, b3, b4v;
                    RHS(t0, t1, t2, t3, t4, b0, b1, b2, b3, b4v);
                    t0 = yf0 + hhf * b0; t1 = yf1 + hhf * b1; t2 = yf2 + hhf * b2;
                    t3 = yf3 + hhf * b3; t4 = yf4 + hhf * b4v;
                    float c0, c1, c2, c3, c4;
                    RHS(t0, t1, t2, t3, t4, c0, c1, c2, c3, c4);
                    t0 = yf0 + h * c0; t1 = yf1 + h * c1; t2 = yf2 + h * c2;
                    t3 = yf3 + h * c3; t4 = yf4 + h * c4;
                    float d0, d1, d2, d3, d4;
                    RHS(t0, t1, t2, t3, t4, d0, d1, d2, d3, d4);
#undef RHS
                    float s6 = h * (1.0f / 6.0f);
                    yf0 = fmaxf(yf0 + s6 * (a0 + 2.f * b0 + 2.f * c0 + d0), 0.f);
                    yf1 = fmaxf(yf1 + s6 * (a1 + 2.f * b1 + 2.f * c1 + d1), 0.f);
                    yf2 = fmaxf(yf2 + s6 * (a2 + 2.f * b2 + 2.f * c2 + d2), 0.f);
                    yf3 = fmaxf(yf3 + s6 * (a3 + 2.f * b3 + 2.f * c3 + d3), 0.f);
                    yf4 = fmaxf(yf4 + s6 * (a4 + 2.f * b4v + 2.f * c4 + d4), 0.f);

                    int bg = bg0 + g;
                    float* yo = out + ((size_t)bg * K + k) * 3;
                    yo[0] = yf0; yo[1] = yf2; yo[2] = yf4;
                    sYobs[g * 4 + 0] = yf0; sYobs[g * 4 + 1] = yf2; sYobs[g * 4 + 2] = yf4;
                    if (k + 1 < K) {
                        sU[g * 4 + 0] = nu0; sU[g * 4 + 1] = nu1; sU[g * 4 + 2] = nu2;
                        if (nflag) {
                            sYtf[g * 4 + 0] = nt0; sYtf[g * 4 + 1] = nt1; sYtf[g * 4 + 2] = nt2;
                        }
                        cu0 = nu0; cu1 = nu1; cu2 = nu2; cdt = ndt;
                    }
                }
            }
            asm volatile("bar.sync 1, 128;" ::: "memory");   // aux-only barrier
            // ---- lift(k+1) ----
            {
                int kk1 = k + 1;
                bool lf = (kk1 % 50) == 0;
                const float* ub = sU + lbb * 4;
                const float* yb = lf ? (sYtf + lbb * 4) : (sYobs + lbb * 4);
                float s = blf;
                s = fmaf(wl0, ub[0], s); s = fmaf(wl1, ub[1], s); s = fmaf(wl2, ub[2], s);
                s = fmaf(wl3, yb[0], s); s = fmaf(wl4, yb[1], s); s = fmaf(wl5, yb[2], s);
                sLift[lbb * LPITCH + lgl] = s * sigm(s);
            }
        }
        __syncthreads();   // BAR_B: sLift(k+1) visible, gh(k+1) done
    }
}

extern "C" void kernel_launch(void* const* d_in, const int* in_sizes, int n_in,
                              void* d_out, int out_size)
{
    const float* y0     = (const float*)d_in[0];
    const float* u_seq  = (const float*)d_in[1];
    const float* dt_seq = (const float*)d_in[2];
    const float* y_seq  = (const float*)d_in[3];
    const float* W_lift = (const float*)d_in[4];
    const float* b_lift = (const float*)d_in[5];
    const float* W_ih   = (const float*)d_in[6];
    const float* W_hh   = (const float*)d_in[7];
    const float* b_ih   = (const float*)d_in[8];
    const float* b_hh   = (const float*)d_in[9];
    const float* W_head = (const float*)d_in[10];
    const float* b_head = (const float*)d_in[11];
    const float* u2y    = (const float*)d_in[12];
    float* out = (float*)d_out;

    int B = in_sizes[0] / 3;
    int K = in_sizes[2] / B;

    cudaFuncSetAttribute(krnn_kernel, cudaFuncAttributeMaxDynamicSharedMemorySize, SMEM_BYTES);
    krnn_kernel<<<B / 4, THREADS, SMEM_BYTES>>>(
        y0, u_seq, dt_seq, y_seq, W_lift, b_lift, W_ih, W_hh,
        b_ih, b_hh, W_head, b_head, u2y, out, B, K);
}

// round 16
// speedup vs baseline: 4.7538x; 1.6921x over previous
#include <cuda_runtime.h>
#include <math.h>

// KineticsRNN R16: exact R5 re-baseline (best measured: 1142.8us).
// 256 mat threads: (i=t>>1, c=t&1) own gate rows (r_i,z_i,n_i), K-half c ->
// shfl.bfly(1) butterfly gives full gates, h_new computed locally.
// 128 aux threads: tail (head+RK4+outputs) overlapped with mat's gh; lift.
// 2 full barriers/step + 1 aux-only named barrier.

#define THREADS 384
#define MATT 256
#define HDIM 128
#define PITCH 136     // W_hh / sH / sWhd pitch (words); K-chunk1 at +68
#define CGAP 68
#define LPITCH 40     // sLift pitch; chunk1 at +20
#define LGAP 20

#define SMEM_FLOATS (384*PITCH + 4*PITCH + 4*LPITCH + 5*PITCH + 16 + 16 + 16)
#define SMEM_BYTES  (SMEM_FLOATS * 4)

typedef unsigned long long u64;

__device__ __forceinline__ u64 fma2(u64 a, u64 b, u64 c) {
    u64 d;
    asm("fma.rn.f32x2 %0, %1, %2, %3;" : "=l"(d) : "l"(a), "l"(b), "l"(c));
    return d;
}
__device__ __forceinline__ float f2sum(u64 v) {
    float2 f;
    asm("mov.b64 {%0, %1}, %2;" : "=f"(f.x), "=f"(f.y) : "l"(v));
    return f.x + f.y;
}
__device__ __forceinline__ float sigm(float x) {
    return __fdividef(1.0f, 1.0f + __expf(-x));
}
__device__ __forceinline__ float tanh_f(float x) {
    return 1.0f - __fdividef(2.0f, __expf(2.0f * x) + 1.0f);
}

__global__ __launch_bounds__(THREADS, 1)
void krnn_kernel(const float* __restrict__ y0,
                 const float* __restrict__ u_seq,
                 const float* __restrict__ dt_seq,
                 const float* __restrict__ y_seq,
                 const float* __restrict__ W_lift,
                 const float* __restrict__ b_lift,
                 const float* __restrict__ W_ih,
                 const float* __restrict__ W_hh,
                 const float* __restrict__ b_ih,
                 const float* __restrict__ b_hh,
                 const float* __restrict__ W_head,
                 const float* __restrict__ b_head,
                 const float* __restrict__ u2y,
                 float* __restrict__ out,
                 int B, int K)
{
    extern __shared__ float sm[];
    float* sWhh  = sm;                       // 384*136 (gapped rows)
    float* sH    = sWhh + 384 * PITCH;       // 4*136 (gapped)
    float* sLift = sH + 4 * PITCH;           // 4*40 (gapped)
    float* sWhd  = sLift + 4 * LPITCH;       // 5*136
    float* sU    = sWhd + 5 * PITCH;         // 4*4
    float* sYobs = sU + 16;                  // 4*4
    float* sYtf  = sYobs + 16;               // 4*4

    const int t   = threadIdx.x;
    const int bg0 = blockIdx.x * 4;

    // ---- stage W_hh gapped: word(row,k) = row*136 + k + 4*(k>=64) ----
    {
        const float4* src = (const float4*)W_hh;
        for (int idx = t; idx < 384 * 32; idx += THREADS) {
            int row = idx >> 5, kb = idx & 31;
            int dst = row * PITCH + 4 * kb + ((kb >> 4) << 2);
            *(float4*)(sWhh + dst) = src[idx];
        }
    }
    for (int idx = t; idx < 5 * HDIM; idx += THREADS)
        sWhd[(idx / HDIM) * PITCH + (idx % HDIM)] = W_head[idx];

    // ================= mat persistent state =================
    const int i = t >> 1, c = t & 1;
    u64 wr_[8], wz_[8], wn_[8];
    float cr = 0, cz = 0, bxn = 0, bhn = 0;
    if (t < MATT) {
        const ulonglong2* pr = (const ulonglong2*)(W_ih + (size_t)i * 32 + 16 * c);
        const ulonglong2* pz = (const ulonglong2*)(W_ih + (size_t)(128 + i) * 32 + 16 * c);
        const ulonglong2* pn = (const ulonglong2*)(W_ih + (size_t)(256 + i) * 32 + 16 * c);
#pragma unroll
        for (int j = 0; j < 4; j++) {
            ulonglong2 vr = pr[j]; wr_[2 * j] = vr.x; wr_[2 * j + 1] = vr.y;
            ulonglong2 vz = pz[j]; wz_[2 * j] = vz.x; wz_[2 * j + 1] = vz.y;
            ulonglong2 vn = pn[j]; wn_[2 * j] = vn.x; wn_[2 * j + 1] = vn.y;
        }
        cr  = b_ih[i] + b_hh[i];
        cz  = b_ih[128 + i] + b_hh[128 + i];
        bxn = b_ih[256 + i];
        bhn = b_hh[256 + i];
    }

    // ================= aux persistent state =================
    const int g   = t - 256;                  // aux index (valid t>=256)
    const int hbh = g / 5, hph = g % 5;       // head map (g<20)
    const int lr  = g >> 2, lbb = g & 3;      // lift map
    const int lgl = lr + ((lr >> 4) << 2);
    float bhd = 0.f;
    float wl0 = 0, wl1 = 0, wl2 = 0, wl3 = 0, wl4 = 0, wl5 = 0, blf = 0;
    float yf0 = 0, yf1 = 0, yf2 = 0, yf3 = 0, yf4 = 0;
    float J00 = 0, J01 = 0, J02 = 0, J10 = 0, J11 = 0, J12 = 0, J20 = 0, J21 = 0, J22 = 0;
    float cu0 = 0, cu1 = 0, cu2 = 0, cdt = 0;
    if (t >= MATT) {
        if (g < 20) bhd = b_head[hph];
        wl0 = W_lift[lr * 6 + 0]; wl1 = W_lift[lr * 6 + 1]; wl2 = W_lift[lr * 6 + 2];
        wl3 = W_lift[lr * 6 + 3]; wl4 = W_lift[lr * 6 + 4]; wl5 = W_lift[lr * 6 + 5];
        blf = b_lift[lr];
        if (g < 4) {
            int bg = bg0 + g;
            yf0 = y0[bg * 3 + 0]; yf2 = y0[bg * 3 + 1]; yf4 = y0[bg * 3 + 2];
            J00 = u2y[0]; J01 = u2y[1]; J02 = u2y[2];
            J10 = u2y[3]; J11 = u2y[4]; J12 = u2y[5];
            J20 = u2y[6]; J21 = u2y[7]; J22 = u2y[8];
            const float* up = u_seq + (size_t)bg * K * 3;
            cu0 = up[0]; cu1 = up[1]; cu2 = up[2];
            cdt = dt_seq[(size_t)bg * K];
            sU[g * 4 + 0] = cu0; sU[g * 4 + 1] = cu1; sU[g * 4 + 2] = cu2;
            sYobs[g * 4 + 0] = yf0; sYobs[g * 4 + 1] = yf2; sYobs[g * 4 + 2] = yf4;
        }
    }
    for (int idx = t; idx < 4 * PITCH; idx += THREADS) sH[idx] = 0.f;
    __syncthreads();

    // ---- prologue: lift(0) ----
    if (t >= MATT) {
        const float* ub = sU + lbb * 4;
        const float* yb = sYobs + lbb * 4;
        float s = blf;
        s = fmaf(wl0, ub[0], s); s = fmaf(wl1, ub[1], s); s = fmaf(wl2, ub[2], s);
        s = fmaf(wl3, yb[0], s); s = fmaf(wl4, yb[1], s); s = fmaf(wl5, yb[2], s);
        sLift[lbb * LPITCH + lgl] = s * sigm(s);
    }
    __syncthreads();

    const size_t theta_base = (size_t)B * K * 3;

    // gh accumulators: start at 0 (h(-1) = 0 -> gh(0) = 0)
    u64 aR0 = 0, aR1 = 0, aR2 = 0, aR3 = 0;
    u64 aZ0 = 0, aZ1 = 0, aZ2 = 0, aZ3 = 0;
    u64 aN0 = 0, aN1 = 0, aN2 = 0, aN3 = 0;   // ghn
    float nu0 = 0, nu1 = 0, nu2 = 0, ndt = 0, nt0 = 0, nt1 = 0, nt2 = 0;
    bool nflag = false;

    for (int k = 0; k < K; k++) {
        if (t < MATT) {
            // ---- gx(k) (r,z merge into aR/aZ; n part separate) ----
            u64 aX0 = 0, aX1 = 0, aX2 = 0, aX3 = 0;
            {
                const ulonglong2* l0 = (const ulonglong2*)(sLift + 0 * LPITCH + LGAP * c);
                const ulonglong2* l1 = (const ulonglong2*)(sLift + 1 * LPITCH + LGAP * c);
                const ulonglong2* l2 = (const ulonglong2*)(sLift + 2 * LPITCH + LGAP * c);
                const ulonglong2* l3 = (const ulonglong2*)(sLift + 3 * LPITCH + LGAP * c);
#pragma unroll
                for (int j = 0; j < 4; j++) {
                    u64 wa = wr_[2 * j], wb = wr_[2 * j + 1];
                    u64 za = wz_[2 * j], zb = wz_[2 * j + 1];
                    u64 na = wn_[2 * j], nb = wn_[2 * j + 1];
                    ulonglong2 v0 = l0[j];
                    aR0 = fma2(wa, v0.x, aR0); aR0 = fma2(wb, v0.y, aR0);
                    aZ0 = fma2(za, v0.x, aZ0); aZ0 = fma2(zb, v0.y, aZ0);
                    aX0 = fma2(na, v0.x, aX0); aX0 = fma2(nb, v0.y, aX0);
                    ulonglong2 v1 = l1[j];
                    aR1 = fma2(wa, v1.x, aR1); aR1 = fma2(wb, v1.y, aR1);
                    aZ1 = fma2(za, v1.x, aZ1); aZ1 = fma2(zb, v1.y, aZ1);
                    aX1 = fma2(na, v1.x, aX1); aX1 = fma2(nb, v1.y, aX1);
                    ulonglong2 v2 = l2[j];
                    aR2 = fma2(wa, v2.x, aR2); aR2 = fma2(wb, v2.y, aR2);
                    aZ2 = fma2(za, v2.x, aZ2); aZ2 = fma2(zb, v2.y, aZ2);
                    aX2 = fma2(na, v2.x, aX2); aX2 = fma2(nb, v2.y, aX2);
                    ulonglong2 v3 = l3[j];
                    aR3 = fma2(wa, v3.x, aR3); aR3 = fma2(wb, v3.y, aR3);
                    aZ3 = fma2(za, v3.x, aZ3); aZ3 = fma2(zb, v3.y, aZ3);
                    aX3 = fma2(na, v3.x, aX3); aX3 = fma2(nb, v3.y, aX3);
                }
            }
            // ---- reduce across K-half pair (bfly ^1) ----
            float r0s = f2sum(aR0), r1s = f2sum(aR1), r2s = f2sum(aR2), r3s = f2sum(aR3);
            float z0s = f2sum(aZ0), z1s = f2sum(aZ1), z2s = f2sum(aZ2), z3s = f2sum(aZ3);
            float x0s = f2sum(aX0), x1s = f2sum(aX1), x2s = f2sum(aX2), x3s = f2sum(aX3);
            float n0s = f2sum(aN0), n1s = f2sum(aN1), n2s = f2sum(aN2), n3s = f2sum(aN3);
            r0s += __shfl_xor_sync(0xffffffffu, r0s, 1);
            r1s += __shfl_xor_sync(0xffffffffu, r1s, 1);
            r2s += __shfl_xor_sync(0xffffffffu, r2s, 1);
            r3s += __shfl_xor_sync(0xffffffffu, r3s, 1);
            z0s += __shfl_xor_sync(0xffffffffu, z0s, 1);
            z1s += __shfl_xor_sync(0xffffffffu, z1s, 1);
            z2s += __shfl_xor_sync(0xffffffffu, z2s, 1);
            z3s += __shfl_xor_sync(0xffffffffu, z3s, 1);
            x0s += __shfl_xor_sync(0xffffffffu, x0s, 1);
            x1s += __shfl_xor_sync(0xffffffffu, x1s, 1);
            x2s += __shfl_xor_sync(0xffffffffu, x2s, 1);
            x3s += __shfl_xor_sync(0xffffffffu, x3s, 1);
            n0s += __shfl_xor_sync(0xffffffffu, n0s, 1);
            n1s += __shfl_xor_sync(0xffffffffu, n1s, 1);
            n2s += __shfl_xor_sync(0xffffffffu, n2s, 1);
            n3s += __shfl_xor_sync(0xffffffffu, n3s, 1);
            // lane c handles batches 2c, 2c+1; compute gates + h_new locally
            float rA = c ? r2s : r0s, rB = c ? r3s : r1s;
            float zA = c ? z2s : z0s, zB = c ? z3s : z1s;
            float xA = c ? x2s : x0s, xB = c ? x3s : x1s;
            float nA = c ? n2s : n0s, nB = c ? n3s : n1s;
            const int bA = 2 * c, bB = 2 * c + 1;
            const int gi = i + ((i >> 6) << 2);
            {
                float r = sigm(rA + cr);
                float z = sigm(zA + cz);
                float n = tanh_f(xA + bxn + r * (nA + bhn));
                float ho = sH[bA * PITCH + gi];
                sH[bA * PITCH + gi] = n + z * (ho - n);
            }
            {
                float r = sigm(rB + cr);
                float z = sigm(zB + cz);
                float n = tanh_f(xB + bxn + r * (nB + bhn));
                float ho = sH[bB * PITCH + gi];
                sH[bB * PITCH + gi] = n + z * (ho - n);
            }
            aR0 = aR1 = aR2 = aR3 = 0;
            aZ0 = aZ1 = aZ2 = aZ3 = 0;
            aN0 = aN1 = aN2 = aN3 = 0;
        } else {
            // ---- prefetch step-(k+1) inputs ----
            nflag = false;
            if (g < 4 && (k + 1) < K) {
                int bg = bg0 + g;
                const float* up = u_seq + ((size_t)bg * K + (k + 1)) * 3;
                nu0 = up[0]; nu1 = up[1]; nu2 = up[2];
                ndt = dt_seq[(size_t)bg * K + (k + 1)];
                nflag = ((k + 1) % 50) == 0;
                if (nflag) {
                    const float* yp = y_seq + ((size_t)bg * K + k) * 3;
                    nt0 = yp[0]; nt1 = yp[1]; nt2 = yp[2];
                }
            }
        }
        __syncthreads();   // BAR_A: sH = h(k) visible

        if (t < MATT) {
            // ---- gh(k+1): W_hh x h(k), overlapped with aux tail ----
            const ulonglong2* wRp = (const ulonglong2*)(sWhh + i * PITCH + CGAP * c);
            const ulonglong2* wZp = (const ulonglong2*)(sWhh + (128 + i) * PITCH + CGAP * c);
            const ulonglong2* wNp = (const ulonglong2*)(sWhh + (256 + i) * PITCH + CGAP * c);
            const ulonglong2* x0 = (const ulonglong2*)(sH + 0 * PITCH + CGAP * c);
            const ulonglong2* x1 = (const ulonglong2*)(sH + 1 * PITCH + CGAP * c);
            const ulonglong2* x2 = (const ulonglong2*)(sH + 2 * PITCH + CGAP * c);
            const ulonglong2* x3 = (const ulonglong2*)(sH + 3 * PITCH + CGAP * c);
#pragma unroll
            for (int j = 0; j < 16; j++) {
                ulonglong2 wR = wRp[j], wZ = wZp[j], wN = wNp[j];
                ulonglong2 v0 = x0[j];
                aR0 = fma2(wR.x, v0.x, aR0); aR0 = fma2(wR.y, v0.y, aR0);
                aZ0 = fma2(wZ.x, v0.x, aZ0); aZ0 = fma2(wZ.y, v0.y, aZ0);
                aN0 = fma2(wN.x, v0.x, aN0); aN0 = fma2(wN.y, v0.y, aN0);
                ulonglong2 v1 = x1[j];
                aR1 = fma2(wR.x, v1.x, aR1); aR1 = fma2(wR.y, v1.y, aR1);
                aZ1 = fma2(wZ.x, v1.x, aZ1); aZ1 = fma2(wZ.y, v1.y, aZ1);
                aN1 = fma2(wN.x, v1.x, aN1); aN1 = fma2(wN.y, v1.y, aN1);
                ulonglong2 v2 = x2[j];
                aR2 = fma2(wR.x, v2.x, aR2); aR2 = fma2(wR.y, v2.y, aR2);
                aZ2 = fma2(wZ.x, v2.x, aZ2); aZ2 = fma2(wZ.y, v2.y, aZ2);
                aN2 = fma2(wN.x, v2.x, aN2); aN2 = fma2(wN.y, v2.y, aN2);
                ulonglong2 v3 = x3[j];
                aR3 = fma2(wR.x, v3.x, aR3); aR3 = fma2(wR.y, v3.y, aR3);
                aZ3 = fma2(wZ.x, v3.x, aZ3); aZ3 = fma2(wZ.y, v3.y, aZ3);
                aN3 = fma2(wN.x, v3.x, aN3); aN3 = fma2(wN.y, v3.y, aN3);
            }
        } else {
            // ---- tail(k): head + RK4, then lift(k+1) ----
            float thv = 0.f;
            if (g < 20) {
                u64 s0 = 0, s1 = 0;
#pragma unroll
                for (int half = 0; half < 2; half++) {
                    const ulonglong2* hr = (const ulonglong2*)(sH + hbh * PITCH + CGAP * half);
                    const ulonglong2* wp = (const ulonglong2*)(sWhd + hph * PITCH + 64 * half);
#pragma unroll
                    for (int jb = 0; jb < 16; jb++) {
                        ulonglong2 h4 = hr[jb];
                        ulonglong2 w4 = wp[jb];
                        s0 = fma2(w4.x, h4.x, s0);
                        s1 = fma2(w4.y, h4.y, s1);
                    }
                }
                float s = f2sum(s0) + f2sum(s1) + bhd;
                thv = 0.001f + 1.999f * sigm(s);
                out[theta_base + ((size_t)(bg0 + hbh) * K + k) * 5 + hph] = thv;
            }
            if (g < 32) {   // warp 8 only (uniform)
                float th0 = __shfl_sync(0xffffffffu, thv, g * 5 + 0);
                float th1 = __shfl_sync(0xffffffffu, thv, g * 5 + 1);
                float th2 = __shfl_sync(0xffffffffu, thv, g * 5 + 2);
                float th3 = __shfl_sync(0xffffffffu, thv, g * 5 + 3);
                float th4 = __shfl_sync(0xffffffffu, thv, g * 5 + 4);
                if (g < 4) {
                    yf0 += cu0 * J00 + cu1 * J10 + cu2 * J20;
                    yf2 += cu0 * J01 + cu1 * J11 + cu2 * J21;
                    yf4 += cu0 * J02 + cu1 * J12 + cu2 * J22;
                    float h  = cdt;
                    float hhf = 0.5f * h;
#define RHS(A_, Bv, C_, D_, E_, d0, d1, d2, d3, d4)                      \
                    {                                                    \
                        float r1 = th0 * (A_) * (Bv);                    \
                        float r2 = th1 * (C_);                           \
                        float r3 = th2 * (C_) * (D_);                    \
                        float r4 = th3 * (E_);                           \
                        float r5 = th4 * (A_);                           \
                        d0 = -r1 - r5; d1 = -r1 + r2; d2 = r1 - r2 - r3; \
                        d3 = -r3 + r4; d4 = r3 - r4 + r5;                \
                    }
                    float a0, a1, a2, a3, a4;
                    RHS(yf0, yf1, yf2, yf3, yf4, a0, a1, a2, a3, a4);
                    float t0 = yf0 + hhf * a0, t1 = yf1 + hhf * a1, t2 = yf2 + hhf * a2,
                          t3 = yf3 + hhf * a3, t4 = yf4 + hhf * a4;
                    float b0, b1, b2, b3, b4v;
                    RHS(t0, t1, t2, t3, t4, b0, b1, b2, b3, b4v);
                    t0 = yf0 + hhf * b0; t1 = yf1 + hhf * b1; t2 = yf2 + hhf * b2;
                    t3 = yf3 + hhf * b3; t4 = yf4 + hhf * b4v;
                    float c0, c1, c2, c3, c4;
                    RHS(t0, t1, t2, t3, t4, c0, c1, c2, c3, c4);
                    t0 = yf0 + h * c0; t1 = yf1 + h * c1; t2 = yf2 + h * c2;
                    t3 = yf3 + h * c3; t4 = yf4 + h * c4;
                    float d0, d1, d2, d3, d4;
                    RHS(t0, t1, t2, t3, t4, d0, d1, d2, d3, d4);
#undef RHS
                    float s6 = h * (1.0f / 6.0f);
                    yf0 = fmaxf(yf0 + s6 * (a0 + 2.f * b0 + 2.f * c0 + d0), 0.f);
                    yf1 = fmaxf(yf1 + s6 * (a1 + 2.f * b1 + 2.f * c1 + d1), 0.f);
                    yf2 = fmaxf(yf2 + s6 * (a2 + 2.f * b2 + 2.f * c2 + d2), 0.f);
                    yf3 = fmaxf(yf3 + s6 * (a3 + 2.f * b3 + 2.f * c3 + d3), 0.f);
                    yf4 = fmaxf(yf4 + s6 * (a4 + 2.f * b4v + 2.f * c4 + d4), 0.f);

                    int bg = bg0 + g;
                    float* yo = out + ((size_t)bg * K + k) * 3;
                    yo[0] = yf0; yo[1] = yf2; yo[2] = yf4;
                    sYobs[g * 4 + 0] = yf0; sYobs[g * 4 + 1] = yf2; sYobs[g * 4 + 2] = yf4;
                    if (k + 1 < K) {
                        sU[g * 4 + 0] = nu0; sU[g * 4 + 1] = nu1; sU[g * 4 + 2] = nu2;
                        if (nflag) {
                            sYtf[g * 4 + 0] = nt0; sYtf[g * 4 + 1] = nt1; sYtf[g * 4 + 2] = nt2;
                        }
                        cu0 = nu0; cu1 = nu1; cu2 = nu2; cdt = ndt;
                    }
                }
            }
            asm volatile("bar.sync 1, 128;" ::: "memory");   // aux-only barrier
            // ---- lift(k+1) ----
            {
                int kk1 = k + 1;
                bool lf = (kk1 % 50) == 0;
                const float* ub = sU + lbb * 4;
                const float* yb = lf ? (sYtf + lbb * 4) : (sYobs + lbb * 4);
                float s = blf;
                s = fmaf(wl0, ub[0], s); s = fmaf(wl1, ub[1], s); s = fmaf(wl2, ub[2], s);
                s = fmaf(wl3, yb[0], s); s = fmaf(wl4, yb[1], s); s = fmaf(wl5, yb[2], s);
                sLift[lbb * LPITCH + lgl] = s * sigm(s);
            }
        }
        __syncthreads();   // BAR_B: sLift(k+1) visible, gh(k+1) done
    }
}

extern "C" void kernel_launch(void* const* d_in, const int* in_sizes, int n_in,
                              void* d_out, int out_size)
{
    const float* y0     = (const float*)d_in[0];
    const float* u_seq  = (const float*)d_in[1];
    const float* dt_seq = (const float*)d_in[2];
    const float* y_seq  = (const float*)d_in[3];
    const float* W_lift = (const float*)d_in[4];
    const float* b_lift = (const float*)d_in[5];
    const float* W_ih   = (const float*)d_in[6];
    const float* W_hh   = (const float*)d_in[7];
    const float* b_ih   = (const float*)d_in[8];
    const float* b_hh   = (const float*)d_in[9];
    const float* W_head = (const float*)d_in[10];
    const float* b_head = (const float*)d_in[11];
    const float* u2y    = (const float*)d_in[12];
    float* out = (float*)d_out;

    int B = in_sizes[0] / 3;
    int K = in_sizes[2] / B;

    cudaFuncSetAttribute(krnn_kernel, cudaFuncAttributeMaxDynamicSharedMemorySize, SMEM_BYTES);
    krnn_kernel<<<B / 4, THREADS, SMEM_BYTES>>>(
        y0, u_seq, dt_seq, y_seq, W_lift, b_lift, W_ih, W_hh,
        b_ih, b_hh, W_head, b_head, u2y, out, B, K);
}

// round 17
// speedup vs baseline: 4.9479x; 1.0408x over previous
#include <cuda_runtime.h>
#include <math.h>

// KineticsRNN R17: confirmed R5 structure + (a) tanh.approx gate activations in
// mat-P2 only (aux theta/silu stay precise), (b) split BAR_A (mat bar.sync 3,256
// + bar.arrive 2,384; aux bar.sync 2,384).
// 256 mat threads: (i=t>>1, c=t&1) own gate rows (r_i,z_i,n_i), K-half c.
// 128 aux threads: tail (head+RK4+outputs) overlapped with mat's gh; lift.

#define THREADS 384
#define MATT 256
#define HDIM 128
#define PITCH 136     // W_hh / sH / sWhd pitch (words); K-chunk1 at +68
#define CGAP 68
#define LPITCH 40     // sLift pitch; chunk1 at +20
#define LGAP 20

#define SMEM_FLOATS (384*PITCH + 4*PITCH + 4*LPITCH + 5*PITCH + 16 + 16 + 16)
#define SMEM_BYTES  (SMEM_FLOATS * 4)

typedef unsigned long long u64;

__device__ __forceinline__ u64 fma2(u64 a, u64 b, u64 c) {
    u64 d;
    asm("fma.rn.f32x2 %0, %1, %2, %3;" : "=l"(d) : "l"(a), "l"(b), "l"(c));
    return d;
}
__device__ __forceinline__ float f2sum(u64 v) {
    float2 f;
    asm("mov.b64 {%0, %1}, %2;" : "=f"(f.x), "=f"(f.y) : "l"(v));
    return f.x + f.y;
}
// precise versions (aux path: theta, silu)
__device__ __forceinline__ float sigm(float x) {
    return __fdividef(1.0f, 1.0f + __expf(-x));
}
// fast versions (mat gate path only)
__device__ __forceinline__ float tanha(float x) {
    float y;
    asm("tanh.approx.f32 %0, %1;" : "=f"(y) : "f"(x));
    return y;
}
__device__ __forceinline__ float sigm_fast(float x) {
    return fmaf(0.5f, tanha(0.5f * x), 0.5f);
}

__global__ __launch_bounds__(THREADS, 1)
void krnn_kernel(const float* __restrict__ y0,
                 const float* __restrict__ u_seq,
                 const float* __restrict__ dt_seq,
                 const float* __restrict__ y_seq,
                 const float* __restrict__ W_lift,
                 const float* __restrict__ b_lift,
                 const float* __restrict__ W_ih,
                 const float* __restrict__ W_hh,
                 const float* __restrict__ b_ih,
                 const float* __restrict__ b_hh,
                 const float* __restrict__ W_head,
                 const float* __restrict__ b_head,
                 const float* __restrict__ u2y,
                 float* __restrict__ out,
                 int B, int K)
{
    extern __shared__ float sm[];
    float* sWhh  = sm;                       // 384*136 (gapped rows)
    float* sH    = sWhh + 384 * PITCH;       // 4*136 (gapped)
    float* sLift = sH + 4 * PITCH;           // 4*40 (gapped)
    float* sWhd  = sLift + 4 * LPITCH;       // 5*136
    float* sU    = sWhd + 5 * PITCH;         // 4*4
    float* sYobs = sU + 16;                  // 4*4
    float* sYtf  = sYobs + 16;               // 4*4

    const int t   = threadIdx.x;
    const int bg0 = blockIdx.x * 4;

    // ---- stage W_hh gapped: word(row,k) = row*136 + k + 4*(k>=64) ----
    {
        const float4* src = (const float4*)W_hh;
        for (int idx = t; idx < 384 * 32; idx += THREADS) {
            int row = idx >> 5, kb = idx & 31;
            int dst = row * PITCH + 4 * kb + ((kb >> 4) << 2);
            *(float4*)(sWhh + dst) = src[idx];
        }
    }
    for (int idx = t; idx < 5 * HDIM; idx += THREADS)
        sWhd[(idx / HDIM) * PITCH + (idx % HDIM)] = W_head[idx];

    // ================= mat persistent state =================
    const int i = t >> 1, c = t & 1;
    u64 wr_[8], wz_[8], wn_[8];
    float cr = 0, cz = 0, bxn = 0, bhn = 0;
    if (t < MATT) {
        const ulonglong2* pr = (const ulonglong2*)(W_ih + (size_t)i * 32 + 16 * c);
        const ulonglong2* pz = (const ulonglong2*)(W_ih + (size_t)(128 + i) * 32 + 16 * c);
        const ulonglong2* pn = (const ulonglong2*)(W_ih + (size_t)(256 + i) * 32 + 16 * c);
#pragma unroll
        for (int j = 0; j < 4; j++) {
            ulonglong2 vr = pr[j]; wr_[2 * j] = vr.x; wr_[2 * j + 1] = vr.y;
            ulonglong2 vz = pz[j]; wz_[2 * j] = vz.x; wz_[2 * j + 1] = vz.y;
            ulonglong2 vn = pn[j]; wn_[2 * j] = vn.x; wn_[2 * j + 1] = vn.y;
        }
        cr  = b_ih[i] + b_hh[i];
        cz  = b_ih[128 + i] + b_hh[128 + i];
        bxn = b_ih[256 + i];
        bhn = b_hh[256 + i];
    }

    // ================= aux persistent state =================
    const int g   = t - 256;                  // aux index (valid t>=256)
    const int hbh = g / 5, hph = g % 5;       // head map (g<20)
    const int lr  = g >> 2, lbb = g & 3;      // lift map
    const int lgl = lr + ((lr >> 4) << 2);
    float bhd = 0.f;
    float wl0 = 0, wl1 = 0, wl2 = 0, wl3 = 0, wl4 = 0, wl5 = 0, blf = 0;
    float yf0 = 0, yf1 = 0, yf2 = 0, yf3 = 0, yf4 = 0;
    float J00 = 0, J01 = 0, J02 = 0, J10 = 0, J11 = 0, J12 = 0, J20 = 0, J21 = 0, J22 = 0;
    float cu0 = 0, cu1 = 0, cu2 = 0, cdt = 0;
    if (t >= MATT) {
        if (g < 20) bhd = b_head[hph];
        wl0 = W_lift[lr * 6 + 0]; wl1 = W_lift[lr * 6 + 1]; wl2 = W_lift[lr * 6 + 2];
        wl3 = W_lift[lr * 6 + 3]; wl4 = W_lift[lr * 6 + 4]; wl5 = W_lift[lr * 6 + 5];
        blf = b_lift[lr];
        if (g < 4) {
            int bg = bg0 + g;
            yf0 = y0[bg * 3 + 0]; yf2 = y0[bg * 3 + 1]; yf4 = y0[bg * 3 + 2];
            J00 = u2y[0]; J01 = u2y[1]; J02 = u2y[2];
            J10 = u2y[3]; J11 = u2y[4]; J12 = u2y[5];
            J20 = u2y[6]; J21 = u2y[7]; J22 = u2y[8];
            const float* up = u_seq + (size_t)bg * K * 3;
            cu0 = up[0]; cu1 = up[1]; cu2 = up[2];
            cdt = dt_seq[(size_t)bg * K];
            sU[g * 4 + 0] = cu0; sU[g * 4 + 1] = cu1; sU[g * 4 + 2] = cu2;
            sYobs[g * 4 + 0] = yf0; sYobs[g * 4 + 1] = yf2; sYobs[g * 4 + 2] = yf4;
        }
    }
    for (int idx = t; idx < 4 * PITCH; idx += THREADS) sH[idx] = 0.f;
    __syncthreads();

    // ---- prologue: lift(0) ----
    if (t >= MATT) {
        const float* ub = sU + lbb * 4;
        const float* yb = sYobs + lbb * 4;
        float s = blf;
        s = fmaf(wl0, ub[0], s); s = fmaf(wl1, ub[1], s); s = fmaf(wl2, ub[2], s);
        s = fmaf(wl3, yb[0], s); s = fmaf(wl4, yb[1], s); s = fmaf(wl5, yb[2], s);
        sLift[lbb * LPITCH + lgl] = s * sigm(s);
    }
    __syncthreads();

    const size_t theta_base = (size_t)B * K * 3;

    // gh accumulators: start at 0 (h(-1) = 0 -> gh(0) = 0)
    u64 aR0 = 0, aR1 = 0, aR2 = 0, aR3 = 0;
    u64 aZ0 = 0, aZ1 = 0, aZ2 = 0, aZ3 = 0;
    u64 aN0 = 0, aN1 = 0, aN2 = 0, aN3 = 0;   // ghn
    float nu0 = 0, nu1 = 0, nu2 = 0, ndt = 0, nt0 = 0, nt1 = 0, nt2 = 0;
    bool nflag = false;

    for (int k = 0; k < K; k++) {
        if (t < MATT) {
            // ---- gx(k) (r,z merge into aR/aZ; n part separate) ----
            u64 aX0 = 0, aX1 = 0, aX2 = 0, aX3 = 0;
            {
                const ulonglong2* l0 = (const ulonglong2*)(sLift + 0 * LPITCH + LGAP * c);
                const ulonglong2* l1 = (const ulonglong2*)(sLift + 1 * LPITCH + LGAP * c);
                const ulonglong2* l2 = (const ulonglong2*)(sLift + 2 * LPITCH + LGAP * c);
                const ulonglong2* l3 = (const ulonglong2*)(sLift + 3 * LPITCH + LGAP * c);
#pragma unroll
                for (int j = 0; j < 4; j++) {
                    u64 wa = wr_[2 * j], wb = wr_[2 * j + 1];
                    u64 za = wz_[2 * j], zb = wz_[2 * j + 1];
                    u64 na = wn_[2 * j], nb = wn_[2 * j + 1];
                    ulonglong2 v0 = l0[j];
                    aR0 = fma2(wa, v0.x, aR0); aR0 = fma2(wb, v0.y, aR0);
                    aZ0 = fma2(za, v0.x, aZ0); aZ0 = fma2(zb, v0.y, aZ0);
                    aX0 = fma2(na, v0.x, aX0); aX0 = fma2(nb, v0.y, aX0);
                    ulonglong2 v1 = l1[j];
                    aR1 = fma2(wa, v1.x, aR1); aR1 = fma2(wb, v1.y, aR1);
                    aZ1 = fma2(za, v1.x, aZ1); aZ1 = fma2(zb, v1.y, aZ1);
                    aX1 = fma2(na, v1.x, aX1); aX1 = fma2(nb, v1.y, aX1);
                    ulonglong2 v2 = l2[j];
                    aR2 = fma2(wa, v2.x, aR2); aR2 = fma2(wb, v2.y, aR2);
                    aZ2 = fma2(za, v2.x, aZ2); aZ2 = fma2(zb, v2.y, aZ2);
                    aX2 = fma2(na, v2.x, aX2); aX2 = fma2(nb, v2.y, aX2);
                    ulonglong2 v3 = l3[j];
                    aR3 = fma2(wa, v3.x, aR3); aR3 = fma2(wb, v3.y, aR3);
                    aZ3 = fma2(za, v3.x, aZ3); aZ3 = fma2(zb, v3.y, aZ3);
                    aX3 = fma2(na, v3.x, aX3); aX3 = fma2(nb, v3.y, aX3);
                }
            }
            // ---- reduce across K-half pair (bfly ^1) ----
            float r0s = f2sum(aR0), r1s = f2sum(aR1), r2s = f2sum(aR2), r3s = f2sum(aR3);
            float z0s = f2sum(aZ0), z1s = f2sum(aZ1), z2s = f2sum(aZ2), z3s = f2sum(aZ3);
            float x0s = f2sum(aX0), x1s = f2sum(aX1), x2s = f2sum(aX2), x3s = f2sum(aX3);
            float n0s = f2sum(aN0), n1s = f2sum(aN1), n2s = f2sum(aN2), n3s = f2sum(aN3);
            r0s += __shfl_xor_sync(0xffffffffu, r0s, 1);
            r1s += __shfl_xor_sync(0xffffffffu, r1s, 1);
            r2s += __shfl_xor_sync(0xffffffffu, r2s, 1);
            r3s += __shfl_xor_sync(0xffffffffu, r3s, 1);
            z0s += __shfl_xor_sync(0xffffffffu, z0s, 1);
            z1s += __shfl_xor_sync(0xffffffffu, z1s, 1);
            z2s += __shfl_xor_sync(0xffffffffu, z2s, 1);
            z3s += __shfl_xor_sync(0xffffffffu, z3s, 1);
            x0s += __shfl_xor_sync(0xffffffffu, x0s, 1);
            x1s += __shfl_xor_sync(0xffffffffu, x1s, 1);
            x2s += __shfl_xor_sync(0xffffffffu, x2s, 1);
            x3s += __shfl_xor_sync(0xffffffffu, x3s, 1);
            n0s += __shfl_xor_sync(0xffffffffu, n0s, 1);
            n1s += __shfl_xor_sync(0xffffffffu, n1s, 1);
            n2s += __shfl_xor_sync(0xffffffffu, n2s, 1);
            n3s += __shfl_xor_sync(0xffffffffu, n3s, 1);
            // lane c handles batches 2c, 2c+1; compute gates + h_new locally
            float rA = c ? r2s : r0s, rB = c ? r3s : r1s;
            float zA = c ? z2s : z0s, zB = c ? z3s : z1s;
            float xA = c ? x2s : x0s, xB = c ? x3s : x1s;
            float nA = c ? n2s : n0s, nB = c ? n3s : n1s;
            const int bA = 2 * c, bB = 2 * c + 1;
            const int gi = i + ((i >> 6) << 2);
            {
                float r = sigm_fast(rA + cr);
                float z = sigm_fast(zA + cz);
                float n = tanha(xA + bxn + r * (nA + bhn));
                float ho = sH[bA * PITCH + gi];
                sH[bA * PITCH + gi] = n + z * (ho - n);
            }
            {
                float r = sigm_fast(rB + cr);
                float z = sigm_fast(zB + cz);
                float n = tanha(xB + bxn + r * (nB + bhn));
                float ho = sH[bB * PITCH + gi];
                sH[bB * PITCH + gi] = n + z * (ho - n);
            }
            aR0 = aR1 = aR2 = aR3 = 0;
            aZ0 = aZ1 = aZ2 = aZ3 = 0;
            aN0 = aN1 = aN2 = aN3 = 0;
        } else {
            // ---- prefetch step-(k+1) inputs ----
            nflag = false;
            if (g < 4 && (k + 1) < K) {
                int bg = bg0 + g;
                const float* up = u_seq + ((size_t)bg * K + (k + 1)) * 3;
                nu0 = up[0]; nu1 = up[1]; nu2 = up[2];
                ndt = dt_seq[(size_t)bg * K + (k + 1)];
                nflag = ((k + 1) % 50) == 0;
                if (nflag) {
                    const float* yp = y_seq + ((size_t)bg * K + k) * 3;
                    nt0 = yp[0]; nt1 = yp[1]; nt2 = yp[2];
                }
            }
        }
        // ---- BAR_A split: mat syncs among itself + arrives; aux waits for mat ----
        if (t < MATT) {
            asm volatile("bar.sync 3, 256;" ::: "memory");
            asm volatile("bar.arrive 2, 384;" ::: "memory");
        } else {
            asm volatile("bar.sync 2, 384;" ::: "memory");
        }

        if (t < MATT) {
            // ---- gh(k+1): W_hh x h(k), overlapped with aux tail ----
            const ulonglong2* wRp = (const ulonglong2*)(sWhh + i * PITCH + CGAP * c);
            const ulonglong2* wZp = (const ulonglong2*)(sWhh + (128 + i) * PITCH + CGAP * c);
            const ulonglong2* wNp = (const ulonglong2*)(sWhh + (256 + i) * PITCH + CGAP * c);
            const ulonglong2* x0 = (const ulonglong2*)(sH + 0 * PITCH + CGAP * c);
            const ulonglong2* x1 = (const ulonglong2*)(sH + 1 * PITCH + CGAP * c);
            const ulonglong2* x2 = (const ulonglong2*)(sH + 2 * PITCH + CGAP * c);
            const ulonglong2* x3 = (const ulonglong2*)(sH + 3 * PITCH + CGAP * c);
#pragma unroll
            for (int j = 0; j < 16; j++) {
                ulonglong2 wR = wRp[j], wZ = wZp[j], wN = wNp[j];
                ulonglong2 v0 = x0[j];
                aR0 = fma2(wR.x, v0.x, aR0); aR0 = fma2(wR.y, v0.y, aR0);
                aZ0 = fma2(wZ.x, v0.x, aZ0); aZ0 = fma2(wZ.y, v0.y, aZ0);
                aN0 = fma2(wN.x, v0.x, aN0); aN0 = fma2(wN.y, v0.y, aN0);
                ulonglong2 v1 = x1[j];
                aR1 = fma2(wR.x, v1.x, aR1); aR1 = fma2(wR.y, v1.y, aR1);
                aZ1 = fma2(wZ.x, v1.x, aZ1); aZ1 = fma2(wZ.y, v1.y, aZ1);
                aN1 = fma2(wN.x, v1.x, aN1); aN1 = fma2(wN.y, v1.y, aN1);
                ulonglong2 v2 = x2[j];
                aR2 = fma2(wR.x, v2.x, aR2); aR2 = fma2(wR.y, v2.y, aR2);
                aZ2 = fma2(wZ.x, v2.x, aZ2); aZ2 = fma2(wZ.y, v2.y, aZ2);
                aN2 = fma2(wN.x, v2.x, aN2); aN2 = fma2(wN.y, v2.y, aN2);
                ulonglong2 v3 = x3[j];
                aR3 = fma2(wR.x, v3.x, aR3); aR3 = fma2(wR.y, v3.y, aR3);
                aZ3 = fma2(wZ.x, v3.x, aZ3); aZ3 = fma2(wZ.y, v3.y, aZ3);
                aN3 = fma2(wN.x, v3.x, aN3); aN3 = fma2(wN.y, v3.y, aN3);
            }
        } else {
            // ---- tail(k): head + RK4, then lift(k+1) ----
            float thv = 0.f;
            if (g < 20) {
                u64 s0 = 0, s1 = 0;
#pragma unroll
                for (int half = 0; half < 2; half++) {
                    const ulonglong2* hr = (const ulonglong2*)(sH + hbh * PITCH + CGAP * half);
                    const ulonglong2* wp = (const ulonglong2*)(sWhd + hph * PITCH + 64 * half);
#pragma unroll
                    for (int jb = 0; jb < 16; jb++) {
                        ulonglong2 h4 = hr[jb];
                        ulonglong2 w4 = wp[jb];
                        s0 = fma2(w4.x, h4.x, s0);
                        s1 = fma2(w4.y, h4.y, s1);
                    }
                }
                float s = f2sum(s0) + f2sum(s1) + bhd;
                thv = 0.001f + 1.999f * sigm(s);
                out[theta_base + ((size_t)(bg0 + hbh) * K + k) * 5 + hph] = thv;
            }
            if (g < 32) {   // warp 8 only (uniform)
                float th0 = __shfl_sync(0xffffffffu, thv, g * 5 + 0);
                float th1 = __shfl_sync(0xffffffffu, thv, g * 5 + 1);
                float th2 = __shfl_sync(0xffffffffu, thv, g * 5 + 2);
                float th3 = __shfl_sync(0xffffffffu, thv, g * 5 + 3);
                float th4 = __shfl_sync(0xffffffffu, thv, g * 5 + 4);
                if (g < 4) {
                    yf0 += cu0 * J00 + cu1 * J10 + cu2 * J20;
                    yf2 += cu0 * J01 + cu1 * J11 + cu2 * J21;
                    yf4 += cu0 * J02 + cu1 * J12 + cu2 * J22;
                    float h  = cdt;
                    float hhf = 0.5f * h;
#define RHS(A_, Bv, C_, D_, E_, d0, d1, d2, d3, d4)                      \
                    {                                                    \
                        float r1 = th0 * (A_) * (Bv);                    \
                        float r2 = th1 * (C_);                           \
                        float r3 = th2 * (C_) * (D_);                    \
                        float r4 = th3 * (E_);                           \
                        float r5 = th4 * (A_);                           \
                        d0 = -r1 - r5; d1 = -r1 + r2; d2 = r1 - r2 - r3; \
                        d3 = -r3 + r4; d4 = r3 - r4 + r5;                \
                    }
                    float a0, a1, a2, a3, a4;
                    RHS(yf0, yf1, yf2, yf3, yf4, a0, a1, a2, a3, a4);
                    float t0 = yf0 + hhf * a0, t1 = yf1 + hhf * a1, t2 = yf2 + hhf * a2,
                          t3 = yf3 + hhf * a3, t4 = yf4 + hhf * a4;
                    float b0, b1, b2, b3, b4v;
                    RHS(t0, t1, t2, t3, t4, b0, b1, b2, b3, b4v);
                    t0 = yf0 + hhf * b0; t1 = yf1 + hhf * b1; t2 = yf2 + hhf * b2;
                    t3 = yf3 + hhf * b3; t4 = yf4 + hhf * b4v;
                    float c0, c1, c2, c3, c4;
                    RHS(t0, t1, t2, t3, t4, c0, c1, c2, c3, c4);
                    t0 = yf0 + h * c0; t1 = yf1 + h * c1; t2 = yf2 + h * c2;
                    t3 = yf3 + h * c3; t4 = yf4 + h * c4;
                    float d0, d1, d2, d3, d4;
                    RHS(t0, t1, t2, t3, t4, d0, d1, d2, d3, d4);
#undef RHS
                    float s6 = h * (1.0f / 6.0f);
                    yf0 = fmaxf(yf0 + s6 * (a0 + 2.f * b0 + 2.f * c0 + d0), 0.f);
                    yf1 = fmaxf(yf1 + s6 * (a1 + 2.f * b1 + 2.f * c1 + d1), 0.f);
                    yf2 = fmaxf(yf2 + s6 * (a2 + 2.f * b2 + 2.f * c2 + d2), 0.f);
                    yf3 = fmaxf(yf3 + s6 * (a3 + 2.f * b3 + 2.f * c3 + d3), 0.f);
                    yf4 = fmaxf(yf4 + s6 * (a4 + 2.f * b4v + 2.f * c4 + d4), 0.f);

                    int bg = bg0 + g;
                    float* yo = out + ((size_t)bg * K + k) * 3;
                    yo[0] = yf0; yo[1] = yf2; yo[2] = yf4;
                    sYobs[g * 4 + 0] = yf0; sYobs[g * 4 + 1] = yf2; sYobs[g * 4 + 2] = yf4;
                    if (k + 1 < K) {
                        sU[g * 4 + 0] = nu0; sU[g * 4 + 1] = nu1; sU[g * 4 + 2] = nu2;
                        if (nflag) {
                            sYtf[g * 4 + 0] = nt0; sYtf[g * 4 + 1] = nt1; sYtf[g * 4 + 2] = nt2;
                        }
                        cu0 = nu0; cu1 = nu1; cu2 = nu2; cdt = ndt;
                    }
                }
            }
            asm volatile("bar.sync 1, 128;" ::: "memory");   // aux-only barrier
            // ---- lift(k+1) ----
            {
                int kk1 = k + 1;
                bool lf = (kk1 % 50) == 0;
                const float* ub = sU + lbb * 4;
                const float* yb = lf ? (sYtf + lbb * 4) : (sYobs + lbb * 4);
                float s = blf;
                s = fmaf(wl0, ub[0], s); s = fmaf(wl1, ub[1], s); s = fmaf(wl2, ub[2], s);
                s = fmaf(wl3, yb[0], s); s = fmaf(wl4, yb[1], s); s = fmaf(wl5, yb[2], s);
                sLift[lbb * LPITCH + lgl] = s * sigm(s);
            }
        }
        __syncthreads();   // BAR_B: sLift(k+1) visible, gh(k+1) done
    }
}

extern "C" void kernel_launch(void* const* d_in, const int* in_sizes, int n_in,
                              void* d_out, int out_size)
{
    const float* y0     = (const float*)d_in[0];
    const float* u_seq  = (const float*)d_in[1];
    const float* dt_seq = (const float*)d_in[2];
    const float* y_seq  = (const float*)d_in[3];
    const float* W_lift = (const float*)d_in[4];
    const float* b_lift = (const float*)d_in[5];
    const float* W_ih   = (const float*)d_in[6];
    const float* W_hh   = (const float*)d_in[7];
    const float* b_ih   = (const float*)d_in[8];
    const float* b_hh   = (const float*)d_in[9];
    const float* W_head = (const float*)d_in[10];
    const float* b_head = (const float*)d_in[11];
    const float* u2y    = (const float*)d_in[12];
    float* out = (float*)d_out;

    int B = in_sizes[0] / 3;
    int K = in_sizes[2] / B;

    cudaFuncSetAttribute(krnn_kernel, cudaFuncAttributeMaxDynamicSharedMemorySize, SMEM_BYTES);
    krnn_kernel<<<B / 4, THREADS, SMEM_BYTES>>>(
        y0, u_seq, dt_seq, y_seq, W_lift, b_lift, W_ih, W_hh,
        b_ih, b_hh, W_head, b_head, u2y, out, B, K);
}